// round 11
// baseline (speedup 1.0000x reference)
#include <cuda_runtime.h>
#include <cuda_bf16.h>
#include <math.h>
#include <stdint.h>

#define SEQ 8192
#define DIM 512

// ---------------------------------------------------------------------------
// Scratch (allocation-free rule: __device__ globals)
// ---------------------------------------------------------------------------
__device__ __nv_bfloat16 g_xh[SEQ * DIM], g_xl[SEQ * DIM];
__device__ __nv_bfloat16 g_Wqh[DIM * DIM], g_Wql[DIM * DIM];
__device__ __nv_bfloat16 g_Wkh[DIM * DIM], g_Wkl[DIM * DIM];
__device__ __nv_bfloat16 g_Wvh[DIM * DIM], g_Wvl[DIM * DIM];
__device__ __nv_bfloat16 g_Qh[SEQ * DIM], g_Ql[SEQ * DIM];
__device__ __nv_bfloat16 g_Kh[SEQ * DIM], g_Kl[SEQ * DIM];
__device__ float         g_V[SEQ * DIM];
__device__ __nv_bfloat16 g_Vth[DIM * SEQ], g_Vtl[DIM * SEQ];
__device__ __nv_bfloat16 g_Ath[(size_t)SEQ * SEQ], g_Atl[(size_t)SEQ * SEQ];

// ---------------------------------------------------------------------------
// PTX helpers (baseline ISA only — tcgen05 unavailable on this toolchain)
// ---------------------------------------------------------------------------
__device__ __forceinline__ uint32_t smem_u32(const void* p) {
    uint32_t a;
    asm("{ .reg .u64 t; cvta.to.shared.u64 t, %1; cvt.u32.u64 %0, t; }" : "=r"(a) : "l"(p));
    return a;
}
__device__ __forceinline__ void cp16(uint32_t dst, const void* src) {
    asm volatile("cp.async.cg.shared.global [%0], [%1], 16;" :: "r"(dst), "l"(src) : "memory");
}
__device__ __forceinline__ void cp_commit() { asm volatile("cp.async.commit_group;" ::: "memory"); }
__device__ __forceinline__ void cp_wait1()  { asm volatile("cp.async.wait_group 1;"  ::: "memory"); }

#define SW128(o) ((o) ^ (((o) >> 3) & 0x70))

#define LDSM4(r, a)                                                              \
    asm volatile("ldmatrix.sync.aligned.m8n8.x4.shared.b16 {%0,%1,%2,%3}, [%4];" \
        : "=r"((r)[0]), "=r"((r)[1]), "=r"((r)[2]), "=r"((r)[3]) : "r"(a))

#define MMA16816(c, a, b0, b1)                                                   \
    asm volatile("mma.sync.aligned.m16n8k16.row.col.f32.bf16.bf16.f32 "          \
        "{%0,%1,%2,%3}, {%4,%5,%6,%7}, {%8,%9}, {%0,%1,%2,%3};"                  \
        : "+f"((c)[0]), "+f"((c)[1]), "+f"((c)[2]), "+f"((c)[3])                 \
        : "r"((a)[0]), "r"((a)[1]), "r"((a)[2]), "r"((a)[3]), "r"(b0), "r"(b1))

// ---------------------------------------------------------------------------
// HMMA NT GEMM: C[M,N] = (Ah+Al)[M,Kd] @ (Bh+Bl)[N,Kd]^T  (3-term split)
// MODE: 0 = QK  (bias, split-bf16 output Ch/Cl)
//       1 = VF  (bias, fp32 output Cf)
//       2 = SC  (causal tile skip, scale, fp32 output)
//       3 = AV  (K truncated to (by+1)*128, fp32 output)
// BM=BN=128, BK=64 (128B rows, SW128). 512 threads, 16 warps x (32x32 tile).
// 3-stage cp.async pipeline, load-before-compute: 3 x 4 x 16KB = 192KB smem.
// ---------------------------------------------------------------------------
#define TILE_B 16384
#define NSTAGE 3
#define SMEM_TILES (NSTAGE * 4 * TILE_B)
#define GEMM_SMEM (SMEM_TILES + 1024)

template<int MODE>
__global__ __launch_bounds__(512) void mma_gemm(
    const __nv_bfloat16* __restrict__ Ah, const __nv_bfloat16* __restrict__ Al,
    const __nv_bfloat16* __restrict__ Bh, const __nv_bfloat16* __restrict__ Bl,
    const float* __restrict__ bias,
    float* __restrict__ Cf, __nv_bfloat16* __restrict__ Ch, __nv_bfloat16* __restrict__ Cl,
    int Nld, int Kd, float scale)
{
    const int bx = blockIdx.x, by = blockIdx.y;
    if (MODE == 2 && bx > by) return;

    extern __shared__ char dsm[];
    uint32_t sb = smem_u32(dsm);
    sb = (sb + 1023) & ~1023u;

    const int tid  = threadIdx.x;
    const int wid  = tid >> 5;
    const int lane = tid & 31;
    const int m0   = (wid >> 2) * 32;   // warp M origin (0,32,64,96)
    const int n0   = (wid & 3) * 32;    // warp N origin (0,32,64,96)

    const int kmax    = (MODE == 3) ? (by + 1) * 128 : Kd;
    const int nchunks = kmax >> 6;      // >= 2 always

    const __nv_bfloat16* P[4];
    P[0] = Ah + (size_t)by * 128 * Kd;
    P[1] = Al + (size_t)by * 128 * Kd;
    P[2] = Bh + (size_t)bx * 128 * Kd;
    P[3] = Bl + (size_t)bx * 128 * Kd;

    // loader: 4 tiles x 128 rows x 8 segs(16B) = 4096 cp / 512 thr
    auto load_chunk = [&](int s, int chunk) {
        const uint32_t stage_base = sb + s * 4 * TILE_B;
        #pragma unroll
        for (int i = 0; i < 2; i++) {
            int idx = tid + i * 512;       // 0..1023
            int row = idx >> 3;
            int seg = idx & 7;
            uint32_t so = SW128((uint32_t)(row * 128 + seg * 16));
            #pragma unroll
            for (int t = 0; t < 4; t++) {
                const __nv_bfloat16* src = P[t] + (size_t)row * Kd + chunk * 64 + seg * 8;
                cp16(stage_base + t * TILE_B + so, src);
            }
        }
        cp_commit();
    };

    float c[2][4][4] = {};

    // ldmatrix lane addressing (SW128: XOR (row&7)<<4 into the 16B-seg bits)
    const int la = lane & 15;                       // A: rows 0..15
    const int sa = lane >> 4;                       // A: k-seg select
    const int lb = (lane & 7) | ((lane >> 4) << 3); // B: rows 0..7 / 8..15
    const int sbg = (lane >> 3) & 1;                // B: k-seg select
    const uint32_t xa = (uint32_t)(lane & 7) << 4;
    const uint32_t aRowOff = (uint32_t)(m0 + la) * 128;
    const uint32_t bRowOff = (uint32_t)(n0 + lb) * 128;

    auto compute = [&](int s) {
        const uint32_t base = sb + s * 4 * TILE_B;
        const uint32_t bAh = base, bAl = base + TILE_B;
        const uint32_t bBh = base + 2 * TILE_B, bBl = base + 3 * TILE_B;
        #pragma unroll
        for (int ks = 0; ks < 4; ks++) {
            const uint32_t ka = ((uint32_t)(ks * 32 + sa * 16)) ^ xa;
            const uint32_t kb = ((uint32_t)(ks * 32 + sbg * 16)) ^ xa;
            uint32_t ah[2][4], al[2][4], bh[4][2], bl[4][2];
            #pragma unroll
            for (int mt = 0; mt < 2; mt++) LDSM4(ah[mt], bAh + aRowOff + mt * 2048 + ka);
            #pragma unroll
            for (int mt = 0; mt < 2; mt++) LDSM4(al[mt], bAl + aRowOff + mt * 2048 + ka);
            #pragma unroll
            for (int np = 0; np < 2; np++) {
                uint32_t t4[4];
                LDSM4(t4, bBh + bRowOff + np * 2048 + kb);
                bh[2 * np][0] = t4[0]; bh[2 * np][1] = t4[1];
                bh[2 * np + 1][0] = t4[2]; bh[2 * np + 1][1] = t4[3];
                LDSM4(t4, bBl + bRowOff + np * 2048 + kb);
                bl[2 * np][0] = t4[0]; bl[2 * np][1] = t4[1];
                bl[2 * np + 1][0] = t4[2]; bl[2 * np + 1][1] = t4[3];
            }
            #pragma unroll
            for (int mt = 0; mt < 2; mt++)
                #pragma unroll
                for (int nt = 0; nt < 4; nt++) {
                    MMA16816(c[mt][nt], ah[mt], bh[nt][0], bh[nt][1]);
                    MMA16816(c[mt][nt], ah[mt], bl[nt][0], bl[nt][1]);
                    MMA16816(c[mt][nt], al[mt], bh[nt][0], bh[nt][1]);
                }
        }
    };

    load_chunk(0, 0);
    load_chunk(1, 1);

    for (int i = 0; i < nchunks; i++) {
        cp_wait1();            // chunk i resident (chunk i+1 may be in flight)
        __syncthreads();       // all warps done with stage (i+2)%3 (read at i-1)
        if (i + 2 < nchunks) load_chunk((i + 2) % NSTAGE, i + 2);
        else cp_commit();      // keep group counting consistent
        compute(i % NSTAGE);
    }

    // Epilogue: C frag -> global. thread: rows g, g+8; col pair 2t.
    const int g = lane >> 2, t = lane & 3;
    #pragma unroll
    for (int mt = 0; mt < 2; mt++) {
        #pragma unroll
        for (int nt = 0; nt < 4; nt++) {
            const int col = bx * 128 + n0 + nt * 8 + t * 2;
            #pragma unroll
            for (int h = 0; h < 2; h++) {
                const int row = by * 128 + m0 + mt * 16 + g + h * 8;
                float v0 = c[mt][nt][2 * h + 0];
                float v1 = c[mt][nt][2 * h + 1];
                if (MODE == 0 || MODE == 1) { v0 += bias[col]; v1 += bias[col + 1]; }
                if (MODE == 2) { v0 *= scale; v1 *= scale; }
                const size_t o = (size_t)row * Nld + col;
                if (MODE == 0) {
                    __nv_bfloat16 h0 = __float2bfloat16(v0);
                    __nv_bfloat16 h1 = __float2bfloat16(v1);
                    __nv_bfloat16 l0 = __float2bfloat16(v0 - __bfloat162float(h0));
                    __nv_bfloat16 l1 = __float2bfloat16(v1 - __bfloat162float(h1));
                    *(__nv_bfloat162*)(Ch + o) = __nv_bfloat162(h0, h1);
                    *(__nv_bfloat162*)(Cl + o) = __nv_bfloat162(l0, l1);
                } else {
                    *(float2*)(Cf + o) = make_float2(v0, v1);
                }
            }
        }
    }
}

// ---------------------------------------------------------------------------
// fp32 -> bf16 hi/lo split (elementwise)
// ---------------------------------------------------------------------------
__global__ __launch_bounds__(256) void split_f32(const float* __restrict__ in,
                                                 __nv_bfloat16* __restrict__ hi,
                                                 __nv_bfloat16* __restrict__ lo, int n4)
{
    int i = blockIdx.x * 256 + threadIdx.x;
    if (i >= n4) return;
    float4 v = ((const float4*)in)[i];
    __nv_bfloat16 h[4], l[4];
    float f[4] = {v.x, v.y, v.z, v.w};
    #pragma unroll
    for (int k = 0; k < 4; k++) {
        h[k] = __float2bfloat16(f[k]);
        l[k] = __float2bfloat16(f[k] - __bfloat162float(h[k]));
    }
    ((__nv_bfloat162*)hi)[i * 2]     = __nv_bfloat162(h[0], h[1]);
    ((__nv_bfloat162*)hi)[i * 2 + 1] = __nv_bfloat162(h[2], h[3]);
    ((__nv_bfloat162*)lo)[i * 2]     = __nv_bfloat162(l[0], l[1]);
    ((__nv_bfloat162*)lo)[i * 2 + 1] = __nv_bfloat162(l[2], l[3]);
}

// ---------------------------------------------------------------------------
// V [SEQ, DIM] -> Vt hi/lo [DIM, SEQ] (transpose + split)
// ---------------------------------------------------------------------------
__global__ __launch_bounds__(256) void transpose_split(const float* __restrict__ V,
                                                       __nv_bfloat16* __restrict__ Vth,
                                                       __nv_bfloat16* __restrict__ Vtl)
{
    __shared__ float t[32][33];
    const int x0 = blockIdx.x * 32;
    const int y0 = blockIdx.y * 32;
    const int tx = threadIdx.x & 31, ty = threadIdx.x >> 5;
    #pragma unroll
    for (int i = 0; i < 32; i += 8)
        t[ty + i][tx] = V[(size_t)(y0 + ty + i) * DIM + x0 + tx];
    __syncthreads();
    #pragma unroll
    for (int i = 0; i < 32; i += 8) {
        float v = t[tx][ty + i];
        __nv_bfloat16 h = __float2bfloat16(v);
        __nv_bfloat16 l = __float2bfloat16(v - __bfloat162float(h));
        size_t o = (size_t)(x0 + ty + i) * SEQ + y0 + tx;
        Vth[o] = h;
        Vtl[o] = l;
    }
}

// ---------------------------------------------------------------------------
// In-place causal softmax; emits attn hi/lo bf16 for the AV GEMM.
// bf16 zero-fill only to the next 128 boundary (AV truncates K there);
// fp32 upper triangle zeroed fully (required output).
// ---------------------------------------------------------------------------
__global__ __launch_bounds__(256) void softmax_causal(float* __restrict__ attn,
                                                      __nv_bfloat16* __restrict__ ah,
                                                      __nv_bfloat16* __restrict__ al)
{
    extern __shared__ float row[];
    __shared__ float red[33];

    const int i = blockIdx.x;
    const int n = i + 1;
    const int tid = threadIdx.x;
    float* p = attn + (size_t)i * SEQ;
    __nv_bfloat16* ph = ah + (size_t)i * SEQ;
    __nv_bfloat16* pl = al + (size_t)i * SEQ;

    float m = -1e30f;
    for (int j = tid; j < n; j += 256) {
        float v = p[j];
        row[j] = v;
        m = fmaxf(m, v);
    }
    #pragma unroll
    for (int o = 16; o; o >>= 1) m = fmaxf(m, __shfl_xor_sync(0xffffffffu, m, o));
    if ((tid & 31) == 0) red[tid >> 5] = m;
    __syncthreads();
    if (tid < 32) {
        float v = (tid < 8) ? red[tid] : -1e30f;
        #pragma unroll
        for (int o = 4; o; o >>= 1) v = fmaxf(v, __shfl_xor_sync(0xffffffffu, v, o));
        if (tid == 0) red[32] = v;
    }
    __syncthreads();
    const float rowmax = red[32];
    __syncthreads();

    float s = 0.0f;
    for (int j = tid; j < n; j += 256) {
        float e = __expf(row[j] - rowmax);
        row[j] = e;
        s += e;
    }
    #pragma unroll
    for (int o = 16; o; o >>= 1) s += __shfl_xor_sync(0xffffffffu, s, o);
    if ((tid & 31) == 0) red[tid >> 5] = s;
    __syncthreads();
    if (tid < 32) {
        float v = (tid < 8) ? red[tid] : 0.0f;
        #pragma unroll
        for (int o = 4; o; o >>= 1) v += __shfl_xor_sync(0xffffffffu, v, o);
        if (tid == 0) red[32] = v;
    }
    __syncthreads();
    const float inv = 1.0f / red[32];

    for (int j = tid; j < n; j += 256) {
        float v = row[j] * inv;
        p[j] = v;
        __nv_bfloat16 h = __float2bfloat16(v);
        ph[j] = h;
        pl[j] = __float2bfloat16(v - __bfloat162float(h));
    }
    const int nend = (n + 127) & ~127;            // AV never reads past this
    const __nv_bfloat16 z = __float2bfloat16(0.0f);
    for (int j = n + tid; j < nend; j += 256) {
        ph[j] = z;
        pl[j] = z;
    }
    for (int j = n + tid; j < SEQ; j += 256) p[j] = 0.0f;
}

// ---------------------------------------------------------------------------
extern "C" void kernel_launch(void* const* d_in, const int* in_sizes, int n_in,
                              void* d_out, int out_size)
{
    const float* x  = (const float*)d_in[0];
    const float* Wq = (const float*)d_in[1];
    const float* bq = (const float*)d_in[2];
    const float* Wk = (const float*)d_in[3];
    const float* bk = (const float*)d_in[4];
    const float* Wv = (const float*)d_in[5];
    const float* bv = (const float*)d_in[6];

    float* out  = (float*)d_out;                 // [SEQ, DIM]
    float* attn = out + (size_t)SEQ * DIM;       // [SEQ, SEQ]

    __nv_bfloat16 *xh, *xl, *Wqh, *Wql, *Wkh, *Wkl, *Wvh, *Wvl;
    __nv_bfloat16 *Qh, *Ql, *Kh, *Kl, *Vth, *Vtl, *Ath, *Atl;
    float* Vf;
    cudaGetSymbolAddress((void**)&xh, g_xh);   cudaGetSymbolAddress((void**)&xl, g_xl);
    cudaGetSymbolAddress((void**)&Wqh, g_Wqh); cudaGetSymbolAddress((void**)&Wql, g_Wql);
    cudaGetSymbolAddress((void**)&Wkh, g_Wkh); cudaGetSymbolAddress((void**)&Wkl, g_Wkl);
    cudaGetSymbolAddress((void**)&Wvh, g_Wvh); cudaGetSymbolAddress((void**)&Wvl, g_Wvl);
    cudaGetSymbolAddress((void**)&Qh, g_Qh);   cudaGetSymbolAddress((void**)&Ql, g_Ql);
    cudaGetSymbolAddress((void**)&Kh, g_Kh);   cudaGetSymbolAddress((void**)&Kl, g_Kl);
    cudaGetSymbolAddress((void**)&Vth, g_Vth); cudaGetSymbolAddress((void**)&Vtl, g_Vtl);
    cudaGetSymbolAddress((void**)&Ath, g_Ath); cudaGetSymbolAddress((void**)&Atl, g_Atl);
    cudaGetSymbolAddress((void**)&Vf, g_V);

    cudaFuncSetAttribute(mma_gemm<0>, cudaFuncAttributeMaxDynamicSharedMemorySize, GEMM_SMEM);
    cudaFuncSetAttribute(mma_gemm<1>, cudaFuncAttributeMaxDynamicSharedMemorySize, GEMM_SMEM);
    cudaFuncSetAttribute(mma_gemm<2>, cudaFuncAttributeMaxDynamicSharedMemorySize, GEMM_SMEM);
    cudaFuncSetAttribute(mma_gemm<3>, cudaFuncAttributeMaxDynamicSharedMemorySize, GEMM_SMEM);

    const float inv_sqrt_d = 0.04419417382415922f;  // 1/sqrt(512)

    // 1) split inputs to bf16 hi/lo
    split_f32<<<(SEQ * DIM / 4 + 255) / 256, 256>>>(x, xh, xl, SEQ * DIM / 4);
    split_f32<<<(DIM * DIM / 4 + 255) / 256, 256>>>(Wq, Wqh, Wql, DIM * DIM / 4);
    split_f32<<<(DIM * DIM / 4 + 255) / 256, 256>>>(Wk, Wkh, Wkl, DIM * DIM / 4);
    split_f32<<<(DIM * DIM / 4 + 255) / 256, 256>>>(Wv, Wvh, Wvl, DIM * DIM / 4);

    // 2) QKV projections (tensor cores via mma.sync)
    dim3 gqkv(DIM / 128, SEQ / 128);
    mma_gemm<0><<<gqkv, 512, GEMM_SMEM>>>(xh, xl, Wqh, Wql, bq, nullptr, Qh, Ql, DIM, DIM, 1.0f);
    mma_gemm<0><<<gqkv, 512, GEMM_SMEM>>>(xh, xl, Wkh, Wkl, bk, nullptr, Kh, Kl, DIM, DIM, 1.0f);
    mma_gemm<1><<<gqkv, 512, GEMM_SMEM>>>(xh, xl, Wvh, Wvl, bv, Vf, nullptr, nullptr, DIM, DIM, 1.0f);

    // 3) V -> Vt hi/lo
    transpose_split<<<dim3(DIM / 32, SEQ / 32), 256>>>(Vf, Vth, Vtl);

    // 4) scores = (Q @ K^T) * inv_sqrt_d (lower-triangle tiles)
    dim3 gsc(SEQ / 128, SEQ / 128);
    mma_gemm<2><<<gsc, 512, GEMM_SMEM>>>(Qh, Ql, Kh, Kl, nullptr, attn, nullptr, nullptr, SEQ, DIM, inv_sqrt_d);

    // 5) causal softmax (fp32 out + bf16 hi/lo for AV)
    softmax_causal<<<SEQ, 256, SEQ * sizeof(float)>>>(attn, Ath, Atl);

    // 6) out = attn @ V  (B = Vt, K truncated per row-block)
    dim3 gav(DIM / 128, SEQ / 128);
    mma_gemm<3><<<gav, 512, GEMM_SMEM>>>(Ath, Atl, Vth, Vtl, nullptr, out, nullptr, nullptr, DIM, SEQ, 1.0f);
}

// round 12
// speedup vs baseline: 1.3908x; 1.3908x over previous
#include <cuda_runtime.h>
#include <cuda_bf16.h>
#include <cuda_fp16.h>
#include <math.h>
#include <stdint.h>

#define SEQ 8192
#define DIM 512

// ---------------------------------------------------------------------------
// Scratch (allocation-free rule: __device__ globals)
// ---------------------------------------------------------------------------
__device__ __nv_bfloat16 g_xh[SEQ * DIM], g_xl[SEQ * DIM];
__device__ __nv_bfloat16 g_Wqh[DIM * DIM], g_Wql[DIM * DIM];
__device__ __nv_bfloat16 g_Wkh[DIM * DIM], g_Wkl[DIM * DIM];
__device__ __nv_bfloat16 g_Wvh[DIM * DIM], g_Wvl[DIM * DIM];
__device__ __nv_bfloat16 g_Qh[SEQ * DIM], g_Ql[SEQ * DIM];
__device__ __nv_bfloat16 g_Kh[SEQ * DIM], g_Kl[SEQ * DIM];
__device__ float         g_V[SEQ * DIM];
__device__ __half        g_Vtf[DIM * SEQ];
__device__ __half        g_Af[(size_t)SEQ * SEQ];

// ---------------------------------------------------------------------------
// PTX helpers (baseline ISA only — tcgen05 unavailable on this toolchain)
// ---------------------------------------------------------------------------
__device__ __forceinline__ uint32_t smem_u32(const void* p) {
    uint32_t a;
    asm("{ .reg .u64 t; cvta.to.shared.u64 t, %1; cvt.u32.u64 %0, t; }" : "=r"(a) : "l"(p));
    return a;
}
__device__ __forceinline__ void cp16(uint32_t dst, const void* src) {
    asm volatile("cp.async.cg.shared.global [%0], [%1], 16;" :: "r"(dst), "l"(src) : "memory");
}
__device__ __forceinline__ void cp_commit() { asm volatile("cp.async.commit_group;" ::: "memory"); }
__device__ __forceinline__ void cp_wait1()  { asm volatile("cp.async.wait_group 1;"  ::: "memory"); }

#define SW128(o) ((o) ^ (((o) >> 3) & 0x70))

#define LDSM4(r, a)                                                              \
    asm volatile("ldmatrix.sync.aligned.m8n8.x4.shared.b16 {%0,%1,%2,%3}, [%4];" \
        : "=r"((r)[0]), "=r"((r)[1]), "=r"((r)[2]), "=r"((r)[3]) : "r"(a))

#define MMA_BF16(c, a, b0, b1)                                                   \
    asm volatile("mma.sync.aligned.m16n8k16.row.col.f32.bf16.bf16.f32 "          \
        "{%0,%1,%2,%3}, {%4,%5,%6,%7}, {%8,%9}, {%0,%1,%2,%3};"                  \
        : "+f"((c)[0]), "+f"((c)[1]), "+f"((c)[2]), "+f"((c)[3])                 \
        : "r"((a)[0]), "r"((a)[1]), "r"((a)[2]), "r"((a)[3]), "r"(b0), "r"(b1))

#define MMA_F16(c, a, b0, b1)                                                    \
    asm volatile("mma.sync.aligned.m16n8k16.row.col.f32.f16.f16.f32 "            \
        "{%0,%1,%2,%3}, {%4,%5,%6,%7}, {%8,%9}, {%0,%1,%2,%3};"                  \
        : "+f"((c)[0]), "+f"((c)[1]), "+f"((c)[2]), "+f"((c)[3])                 \
        : "r"((a)[0]), "r"((a)[1]), "r"((a)[2]), "r"((a)[3]), "r"(b0), "r"(b1))

// ---------------------------------------------------------------------------
// HMMA NT GEMM.
// MODE 0 = QK   3-term bf16 split, bias, split-bf16 output Ch/Cl
// MODE 1 = VF   3-term bf16 split, bias, fp32 output Cf
// MODE 2 = SC   3-term bf16 split, causal tile skip, scale, fp32 output
// MODE 3 = AV   SINGLE-term fp16, K truncated to (by+1)*128, fp32 output
// BM=BN=128, BK=64 (128B rows, SW128). 512 threads, 16 warps x (32x32 tile).
// 2-stage cp.async double buffer. Tiles/chunk: 4 (modes 0-2) or 2 (mode 3).
// ---------------------------------------------------------------------------
#define TILE_B 16384
#define GEMM_SMEM (8 * TILE_B + 1024)

template<int MODE>
__global__ __launch_bounds__(512) void mma_gemm(
    const __nv_bfloat16* __restrict__ Ah, const __nv_bfloat16* __restrict__ Al,
    const __nv_bfloat16* __restrict__ Bh, const __nv_bfloat16* __restrict__ Bl,
    const float* __restrict__ bias,
    float* __restrict__ Cf, __nv_bfloat16* __restrict__ Ch, __nv_bfloat16* __restrict__ Cl,
    int Nld, int Kd, float scale)
{
    constexpr int NT = (MODE == 3) ? 2 : 4;   // tiles per chunk
    const int bx = blockIdx.x, by = blockIdx.y;
    if (MODE == 2 && bx > by) return;

    extern __shared__ char dsm[];
    uint32_t sb = smem_u32(dsm);
    sb = (sb + 1023) & ~1023u;

    const int tid  = threadIdx.x;
    const int wid  = tid >> 5;
    const int lane = tid & 31;
    const int m0   = (wid >> 2) * 32;   // warp M origin (0,32,64,96)
    const int n0   = (wid & 3) * 32;    // warp N origin (0,32,64,96)

    const int kmax    = (MODE == 3) ? (by + 1) * 128 : Kd;
    const int nchunks = kmax >> 6;      // >= 2 always

    const __nv_bfloat16* P[NT];
    if (MODE == 3) {
        P[0] = Ah + (size_t)by * 128 * Kd;   // attn fp16 (reinterpreted)
        P[1] = Bh + (size_t)bx * 128 * Kd;   // Vt fp16 (reinterpreted)
    } else {
        P[0] = Ah + (size_t)by * 128 * Kd;
        P[1] = Al + (size_t)by * 128 * Kd;
        P[2] = Bh + (size_t)bx * 128 * Kd;
        P[3] = Bl + (size_t)bx * 128 * Kd;
    }

    // loader: NT tiles x 128 rows x 8 segs(16B) = NT*1024 cp / 512 thr
    auto load_chunk = [&](int s, int chunk) {
        const uint32_t stage_base = sb + s * NT * TILE_B;
        #pragma unroll
        for (int i = 0; i < 2; i++) {
            int idx = tid + i * 512;       // 0..1023
            int row = idx >> 3;
            int seg = idx & 7;
            uint32_t so = SW128((uint32_t)(row * 128 + seg * 16));
            #pragma unroll
            for (int t = 0; t < NT; t++) {
                const __nv_bfloat16* src = P[t] + (size_t)row * Kd + chunk * 64 + seg * 8;
                cp16(stage_base + t * TILE_B + so, src);
            }
        }
        cp_commit();
    };

    float c[2][4][4] = {};

    // ldmatrix lane addressing (SW128: XOR (row&7)<<4 into the 16B-seg bits)
    const int la = lane & 15;                       // A: rows 0..15
    const int sa = lane >> 4;                       // A: k-seg select
    const int lb = (lane & 7) | ((lane >> 4) << 3); // B: rows 0..7 / 8..15
    const int sbg = (lane >> 3) & 1;                // B: k-seg select
    const uint32_t xa = (uint32_t)(lane & 7) << 4;
    const uint32_t aRowOff = (uint32_t)(m0 + la) * 128;
    const uint32_t bRowOff = (uint32_t)(n0 + lb) * 128;

    auto compute = [&](int s) {
        const uint32_t base = sb + s * NT * TILE_B;
        #pragma unroll
        for (int ks = 0; ks < 4; ks++) {
            const uint32_t ka = ((uint32_t)(ks * 32 + sa * 16)) ^ xa;
            const uint32_t kb = ((uint32_t)(ks * 32 + sbg * 16)) ^ xa;
            if (MODE == 3) {
                // single fp16 term: A tile at base, B tile at base+TILE_B
                uint32_t ah[2][4], bh[4][2];
                #pragma unroll
                for (int mt = 0; mt < 2; mt++) LDSM4(ah[mt], base + aRowOff + mt * 2048 + ka);
                #pragma unroll
                for (int np = 0; np < 2; np++) {
                    uint32_t t4[4];
                    LDSM4(t4, base + TILE_B + bRowOff + np * 2048 + kb);
                    bh[2 * np][0] = t4[0]; bh[2 * np][1] = t4[1];
                    bh[2 * np + 1][0] = t4[2]; bh[2 * np + 1][1] = t4[3];
                }
                #pragma unroll
                for (int mt = 0; mt < 2; mt++)
                    #pragma unroll
                    for (int nt = 0; nt < 4; nt++)
                        MMA_F16(c[mt][nt], ah[mt], bh[nt][0], bh[nt][1]);
            } else {
                const uint32_t bAh = base, bAl = base + TILE_B;
                const uint32_t bBh = base + 2 * TILE_B, bBl = base + 3 * TILE_B;
                uint32_t ah[2][4], al[2][4], bh[4][2], bl[4][2];
                #pragma unroll
                for (int mt = 0; mt < 2; mt++) LDSM4(ah[mt], bAh + aRowOff + mt * 2048 + ka);
                #pragma unroll
                for (int mt = 0; mt < 2; mt++) LDSM4(al[mt], bAl + aRowOff + mt * 2048 + ka);
                #pragma unroll
                for (int np = 0; np < 2; np++) {
                    uint32_t t4[4];
                    LDSM4(t4, bBh + bRowOff + np * 2048 + kb);
                    bh[2 * np][0] = t4[0]; bh[2 * np][1] = t4[1];
                    bh[2 * np + 1][0] = t4[2]; bh[2 * np + 1][1] = t4[3];
                    LDSM4(t4, bBl + bRowOff + np * 2048 + kb);
                    bl[2 * np][0] = t4[0]; bl[2 * np][1] = t4[1];
                    bl[2 * np + 1][0] = t4[2]; bl[2 * np + 1][1] = t4[3];
                }
                #pragma unroll
                for (int mt = 0; mt < 2; mt++)
                    #pragma unroll
                    for (int nt = 0; nt < 4; nt++) {
                        MMA_BF16(c[mt][nt], ah[mt], bh[nt][0], bh[nt][1]);
                        MMA_BF16(c[mt][nt], ah[mt], bl[nt][0], bl[nt][1]);
                        MMA_BF16(c[mt][nt], al[mt], bh[nt][0], bh[nt][1]);
                    }
            }
        }
    };

    load_chunk(0, 0);
    load_chunk(1, 1);

    for (int i = 0; i < nchunks; i++) {
        const int s = i & 1;
        cp_wait1();
        __syncthreads();
        compute(s);
        __syncthreads();
        if (i + 2 < nchunks) load_chunk(s, i + 2);
        else cp_commit();
    }

    // Epilogue: C frag -> global. thread: rows g, g+8; col pair 2t.
    const int g = lane >> 2, t = lane & 3;
    #pragma unroll
    for (int mt = 0; mt < 2; mt++) {
        #pragma unroll
        for (int nt = 0; nt < 4; nt++) {
            const int col = bx * 128 + n0 + nt * 8 + t * 2;
            #pragma unroll
            for (int h = 0; h < 2; h++) {
                const int row = by * 128 + m0 + mt * 16 + g + h * 8;
                float v0 = c[mt][nt][2 * h + 0];
                float v1 = c[mt][nt][2 * h + 1];
                if (MODE == 0 || MODE == 1) { v0 += bias[col]; v1 += bias[col + 1]; }
                if (MODE == 2) { v0 *= scale; v1 *= scale; }
                const size_t o = (size_t)row * Nld + col;
                if (MODE == 0) {
                    __nv_bfloat16 h0 = __float2bfloat16(v0);
                    __nv_bfloat16 h1 = __float2bfloat16(v1);
                    __nv_bfloat16 l0 = __float2bfloat16(v0 - __bfloat162float(h0));
                    __nv_bfloat16 l1 = __float2bfloat16(v1 - __bfloat162float(h1));
                    *(__nv_bfloat162*)(Ch + o) = __nv_bfloat162(h0, h1);
                    *(__nv_bfloat162*)(Cl + o) = __nv_bfloat162(l0, l1);
                } else {
                    *(float2*)(Cf + o) = make_float2(v0, v1);
                }
            }
        }
    }
}

// ---------------------------------------------------------------------------
// fp32 -> bf16 hi/lo split (elementwise)
// ---------------------------------------------------------------------------
__global__ __launch_bounds__(256) void split_f32(const float* __restrict__ in,
                                                 __nv_bfloat16* __restrict__ hi,
                                                 __nv_bfloat16* __restrict__ lo, int n4)
{
    int i = blockIdx.x * 256 + threadIdx.x;
    if (i >= n4) return;
    float4 v = ((const float4*)in)[i];
    __nv_bfloat16 h[4], l[4];
    float f[4] = {v.x, v.y, v.z, v.w};
    #pragma unroll
    for (int k = 0; k < 4; k++) {
        h[k] = __float2bfloat16(f[k]);
        l[k] = __float2bfloat16(f[k] - __bfloat162float(h[k]));
    }
    ((__nv_bfloat162*)hi)[i * 2]     = __nv_bfloat162(h[0], h[1]);
    ((__nv_bfloat162*)hi)[i * 2 + 1] = __nv_bfloat162(h[2], h[3]);
    ((__nv_bfloat162*)lo)[i * 2]     = __nv_bfloat162(l[0], l[1]);
    ((__nv_bfloat162*)lo)[i * 2 + 1] = __nv_bfloat162(l[2], l[3]);
}

// ---------------------------------------------------------------------------
// V [SEQ, DIM] -> Vt fp16 [DIM, SEQ] (transpose + convert)
// ---------------------------------------------------------------------------
__global__ __launch_bounds__(256) void transpose_half(const float* __restrict__ V,
                                                      __half* __restrict__ Vtf)
{
    __shared__ float t[32][33];
    const int x0 = blockIdx.x * 32;
    const int y0 = blockIdx.y * 32;
    const int tx = threadIdx.x & 31, ty = threadIdx.x >> 5;
    #pragma unroll
    for (int i = 0; i < 32; i += 8)
        t[ty + i][tx] = V[(size_t)(y0 + ty + i) * DIM + x0 + tx];
    __syncthreads();
    #pragma unroll
    for (int i = 0; i < 32; i += 8) {
        float v = t[tx][ty + i];
        Vtf[(size_t)(x0 + ty + i) * SEQ + y0 + tx] = __float2half_rn(v);
    }
}

// ---------------------------------------------------------------------------
// In-place causal softmax; emits attn fp16 for the AV GEMM.
// fp16 zero-fill only to the next 128 boundary (AV truncates K there);
// fp32 upper triangle zeroed fully (required output).
// ---------------------------------------------------------------------------
__global__ __launch_bounds__(256) void softmax_causal(float* __restrict__ attn,
                                                      __half* __restrict__ af)
{
    extern __shared__ float row[];
    __shared__ float red[33];

    const int i = blockIdx.x;
    const int n = i + 1;
    const int tid = threadIdx.x;
    float* p = attn + (size_t)i * SEQ;
    __half* pf = af + (size_t)i * SEQ;

    float m = -1e30f;
    for (int j = tid; j < n; j += 256) {
        float v = p[j];
        row[j] = v;
        m = fmaxf(m, v);
    }
    #pragma unroll
    for (int o = 16; o; o >>= 1) m = fmaxf(m, __shfl_xor_sync(0xffffffffu, m, o));
    if ((tid & 31) == 0) red[tid >> 5] = m;
    __syncthreads();
    if (tid < 32) {
        float v = (tid < 8) ? red[tid] : -1e30f;
        #pragma unroll
        for (int o = 4; o; o >>= 1) v = fmaxf(v, __shfl_xor_sync(0xffffffffu, v, o));
        if (tid == 0) red[32] = v;
    }
    __syncthreads();
    const float rowmax = red[32];
    __syncthreads();

    float s = 0.0f;
    for (int j = tid; j < n; j += 256) {
        float e = __expf(row[j] - rowmax);
        row[j] = e;
        s += e;
    }
    #pragma unroll
    for (int o = 16; o; o >>= 1) s += __shfl_xor_sync(0xffffffffu, s, o);
    if ((tid & 31) == 0) red[tid >> 5] = s;
    __syncthreads();
    if (tid < 32) {
        float v = (tid < 8) ? red[tid] : 0.0f;
        #pragma unroll
        for (int o = 4; o; o >>= 1) v += __shfl_xor_sync(0xffffffffu, v, o);
        if (tid == 0) red[32] = v;
    }
    __syncthreads();
    const float inv = 1.0f / red[32];

    for (int j = tid; j < n; j += 256) {
        float v = row[j] * inv;
        p[j] = v;
        pf[j] = __float2half_rn(v);
    }
    const int nend = (n + 127) & ~127;            // AV never reads past this
    const __half z = __float2half_rn(0.0f);
    for (int j = n + tid; j < nend; j += 256) pf[j] = z;
    for (int j = n + tid; j < SEQ; j += 256) p[j] = 0.0f;
}

// ---------------------------------------------------------------------------
extern "C" void kernel_launch(void* const* d_in, const int* in_sizes, int n_in,
                              void* d_out, int out_size)
{
    const float* x  = (const float*)d_in[0];
    const float* Wq = (const float*)d_in[1];
    const float* bq = (const float*)d_in[2];
    const float* Wk = (const float*)d_in[3];
    const float* bk = (const float*)d_in[4];
    const float* Wv = (const float*)d_in[5];
    const float* bv = (const float*)d_in[6];

    float* out  = (float*)d_out;                 // [SEQ, DIM]
    float* attn = out + (size_t)SEQ * DIM;       // [SEQ, SEQ]

    __nv_bfloat16 *xh, *xl, *Wqh, *Wql, *Wkh, *Wkl, *Wvh, *Wvl;
    __nv_bfloat16 *Qh, *Ql, *Kh, *Kl;
    __half *Vtf, *Af;
    float* Vf;
    cudaGetSymbolAddress((void**)&xh, g_xh);   cudaGetSymbolAddress((void**)&xl, g_xl);
    cudaGetSymbolAddress((void**)&Wqh, g_Wqh); cudaGetSymbolAddress((void**)&Wql, g_Wql);
    cudaGetSymbolAddress((void**)&Wkh, g_Wkh); cudaGetSymbolAddress((void**)&Wkl, g_Wkl);
    cudaGetSymbolAddress((void**)&Wvh, g_Wvh); cudaGetSymbolAddress((void**)&Wvl, g_Wvl);
    cudaGetSymbolAddress((void**)&Qh, g_Qh);   cudaGetSymbolAddress((void**)&Ql, g_Ql);
    cudaGetSymbolAddress((void**)&Kh, g_Kh);   cudaGetSymbolAddress((void**)&Kl, g_Kl);
    cudaGetSymbolAddress((void**)&Vtf, g_Vtf); cudaGetSymbolAddress((void**)&Af, g_Af);
    cudaGetSymbolAddress((void**)&Vf, g_V);

    cudaFuncSetAttribute(mma_gemm<0>, cudaFuncAttributeMaxDynamicSharedMemorySize, GEMM_SMEM);
    cudaFuncSetAttribute(mma_gemm<1>, cudaFuncAttributeMaxDynamicSharedMemorySize, GEMM_SMEM);
    cudaFuncSetAttribute(mma_gemm<2>, cudaFuncAttributeMaxDynamicSharedMemorySize, GEMM_SMEM);
    cudaFuncSetAttribute(mma_gemm<3>, cudaFuncAttributeMaxDynamicSharedMemorySize, GEMM_SMEM);

    const float inv_sqrt_d = 0.04419417382415922f;  // 1/sqrt(512)

    // 1) split inputs to bf16 hi/lo
    split_f32<<<(SEQ * DIM / 4 + 255) / 256, 256>>>(x, xh, xl, SEQ * DIM / 4);
    split_f32<<<(DIM * DIM / 4 + 255) / 256, 256>>>(Wq, Wqh, Wql, DIM * DIM / 4);
    split_f32<<<(DIM * DIM / 4 + 255) / 256, 256>>>(Wk, Wkh, Wkl, DIM * DIM / 4);
    split_f32<<<(DIM * DIM / 4 + 255) / 256, 256>>>(Wv, Wvh, Wvl, DIM * DIM / 4);

    // 2) QKV projections (3-term bf16 mma.sync)
    dim3 gqkv(DIM / 128, SEQ / 128);
    mma_gemm<0><<<gqkv, 512, GEMM_SMEM>>>(xh, xl, Wqh, Wql, bq, nullptr, Qh, Ql, DIM, DIM, 1.0f);
    mma_gemm<0><<<gqkv, 512, GEMM_SMEM>>>(xh, xl, Wkh, Wkl, bk, nullptr, Kh, Kl, DIM, DIM, 1.0f);
    mma_gemm<1><<<gqkv, 512, GEMM_SMEM>>>(xh, xl, Wvh, Wvl, bv, Vf, nullptr, nullptr, DIM, DIM, 1.0f);

    // 3) V -> Vt fp16
    transpose_half<<<dim3(DIM / 32, SEQ / 32), 256>>>(Vf, Vtf);

    // 4) scores = (Q @ K^T) * inv_sqrt_d (lower-triangle tiles, 3-term bf16)
    dim3 gsc(SEQ / 128, SEQ / 128);
    mma_gemm<2><<<gsc, 512, GEMM_SMEM>>>(Qh, Ql, Kh, Kl, nullptr, attn, nullptr, nullptr, SEQ, DIM, inv_sqrt_d);

    // 5) causal softmax (fp32 out + fp16 attn for AV)
    softmax_causal<<<SEQ, 256, SEQ * sizeof(float)>>>(attn, Af);

    // 6) out = attn @ V  (single-term fp16, K truncated per row-block)
    dim3 gav(DIM / 128, SEQ / 128);
    mma_gemm<3><<<gav, 512, GEMM_SMEM>>>((const __nv_bfloat16*)Af, nullptr,
                                         (const __nv_bfloat16*)Vtf, nullptr,
                                         nullptr, out, nullptr, nullptr, DIM, SEQ, 1.0f);
}

// round 14
// speedup vs baseline: 1.7865x; 1.2845x over previous
#include <cuda_runtime.h>
#include <cuda_bf16.h>
#include <cuda_fp16.h>
#include <math.h>
#include <stdint.h>

#define SEQ 8192
#define DIM 512

// ---------------------------------------------------------------------------
// Scratch (allocation-free rule: __device__ globals)
// ---------------------------------------------------------------------------
__device__ __nv_bfloat16 g_xh[SEQ * DIM], g_xl[SEQ * DIM];
__device__ __nv_bfloat16 g_Wqh[DIM * DIM], g_Wql[DIM * DIM];
__device__ __nv_bfloat16 g_Wkh[DIM * DIM], g_Wkl[DIM * DIM];
__device__ __nv_bfloat16 g_Wvh[DIM * DIM], g_Wvl[DIM * DIM];
__device__ __half        g_Qf[SEQ * DIM];
__device__ __half        g_Kf[SEQ * DIM];
__device__ float         g_V[SEQ * DIM];
__device__ __half        g_Vtf[DIM * SEQ];
__device__ __half        g_Af[(size_t)SEQ * SEQ];

// ---------------------------------------------------------------------------
// PTX helpers (baseline ISA only — tcgen05 unavailable on this toolchain)
// ---------------------------------------------------------------------------
__device__ __forceinline__ uint32_t smem_u32(const void* p) {
    uint32_t a;
    asm("{ .reg .u64 t; cvta.to.shared.u64 t, %1; cvt.u32.u64 %0, t; }" : "=r"(a) : "l"(p));
    return a;
}
__device__ __forceinline__ void cp16(uint32_t dst, const void* src) {
    asm volatile("cp.async.cg.shared.global [%0], [%1], 16;" :: "r"(dst), "l"(src) : "memory");
}
__device__ __forceinline__ void cp_commit() { asm volatile("cp.async.commit_group;" ::: "memory"); }
__device__ __forceinline__ void cp_wait1()  { asm volatile("cp.async.wait_group 1;"  ::: "memory"); }

#define SW128(o) ((o) ^ (((o) >> 3) & 0x70))

#define LDSM4(r, a)                                                              \
    asm volatile("ldmatrix.sync.aligned.m8n8.x4.shared.b16 {%0,%1,%2,%3}, [%4];" \
        : "=r"((r)[0]), "=r"((r)[1]), "=r"((r)[2]), "=r"((r)[3]) : "r"(a))

#define MMA_BF16(c, a, b0, b1)                                                   \
    asm volatile("mma.sync.aligned.m16n8k16.row.col.f32.bf16.bf16.f32 "          \
        "{%0,%1,%2,%3}, {%4,%5,%6,%7}, {%8,%9}, {%0,%1,%2,%3};"                  \
        : "+f"((c)[0]), "+f"((c)[1]), "+f"((c)[2]), "+f"((c)[3])                 \
        : "r"((a)[0]), "r"((a)[1]), "r"((a)[2]), "r"((a)[3]), "r"(b0), "r"(b1))

#define MMA_F16(c, a, b0, b1)                                                    \
    asm volatile("mma.sync.aligned.m16n8k16.row.col.f32.f16.f16.f32 "            \
        "{%0,%1,%2,%3}, {%4,%5,%6,%7}, {%8,%9}, {%0,%1,%2,%3};"                  \
        : "+f"((c)[0]), "+f"((c)[1]), "+f"((c)[2]), "+f"((c)[3])                 \
        : "r"((a)[0]), "r"((a)[1]), "r"((a)[2]), "r"((a)[3]), "r"(b0), "r"(b1))

// ---------------------------------------------------------------------------
// HMMA NT GEMM.
// MODE 0 = proj QK  3-term bf16 split, bias, fp16 output Chf
// MODE 1 = proj V   3-term bf16 split, bias, fp32 output Cf
// MODE 2 = scores   single-term fp16, causal tile skip, scale, fp32 output
// MODE 3 = AV       single-term fp16, K truncated to (by+1)*128, fp32 output
// BM=BN=128, BK=64 (128B rows, SW128). 512 threads, 16 warps x (32x32 tile).
// 2-stage cp.async double buffer. Tiles/chunk: 4 (modes 0-1) or 2 (modes 2-3).
// ---------------------------------------------------------------------------
#define TILE_B 16384
#define GEMM_SMEM (8 * TILE_B + 1024)

template<int MODE>
__global__ __launch_bounds__(512) void mma_gemm(
    const __nv_bfloat16* __restrict__ Ah, const __nv_bfloat16* __restrict__ Al,
    const __nv_bfloat16* __restrict__ Bh, const __nv_bfloat16* __restrict__ Bl,
    const float* __restrict__ bias,
    float* __restrict__ Cf, __half* __restrict__ Chf,
    int Nld, int Kd, float scale)
{
    constexpr int NT = (MODE >= 2) ? 2 : 4;   // tiles per chunk
    const int bx = blockIdx.x, by = blockIdx.y;
    if (MODE == 2 && bx > by) return;

    extern __shared__ char dsm[];
    uint32_t sb = smem_u32(dsm);
    sb = (sb + 1023) & ~1023u;

    const int tid  = threadIdx.x;
    const int wid  = tid >> 5;
    const int lane = tid & 31;
    const int m0   = (wid >> 2) * 32;   // warp M origin (0,32,64,96)
    const int n0   = (wid & 3) * 32;    // warp N origin (0,32,64,96)

    const int kmax    = (MODE == 3) ? (by + 1) * 128 : Kd;
    const int nchunks = kmax >> 6;      // >= 2 always

    const __nv_bfloat16* P[NT];
    if (MODE >= 2) {
        P[0] = Ah + (size_t)by * 128 * Kd;   // fp16 data (reinterpreted)
        P[1] = Bh + (size_t)bx * 128 * Kd;
    } else {
        P[0] = Ah + (size_t)by * 128 * Kd;
        P[1] = Al + (size_t)by * 128 * Kd;
        P[2] = Bh + (size_t)bx * 128 * Kd;
        P[3] = Bl + (size_t)bx * 128 * Kd;
    }

    // loader: NT tiles x 128 rows x 8 segs(16B) per chunk
    auto load_chunk = [&](int s, int chunk) {
        const uint32_t stage_base = sb + s * NT * TILE_B;
        #pragma unroll
        for (int i = 0; i < 2; i++) {
            int idx = tid + i * 512;       // 0..1023
            int row = idx >> 3;
            int seg = idx & 7;
            uint32_t so = SW128((uint32_t)(row * 128 + seg * 16));
            #pragma unroll
            for (int t = 0; t < NT; t++) {
                const __nv_bfloat16* src = P[t] + (size_t)row * Kd + chunk * 64 + seg * 8;
                cp16(stage_base + t * TILE_B + so, src);
            }
        }
        cp_commit();
    };

    float c[2][4][4] = {};

    // ldmatrix lane addressing (SW128: XOR (row&7)<<4 into the 16B-seg bits)
    const int la = lane & 15;                       // A: rows 0..15
    const int sa = lane >> 4;                       // A: k-seg select
    const int lb = (lane & 7) | ((lane >> 4) << 3); // B: rows 0..7 / 8..15
    const int sbg = (lane >> 3) & 1;                // B: k-seg select
    const uint32_t xa = (uint32_t)(lane & 7) << 4;
    const uint32_t aRowOff = (uint32_t)(m0 + la) * 128;
    const uint32_t bRowOff = (uint32_t)(n0 + lb) * 128;

    auto compute = [&](int s) {
        const uint32_t base = sb + s * NT * TILE_B;
        #pragma unroll
        for (int ks = 0; ks < 4; ks++) {
            const uint32_t ka = ((uint32_t)(ks * 32 + sa * 16)) ^ xa;
            const uint32_t kb = ((uint32_t)(ks * 32 + sbg * 16)) ^ xa;
            if (MODE >= 2) {
                // single fp16 term: A tile at base, B tile at base+TILE_B
                uint32_t ah[2][4], bh[4][2];
                #pragma unroll
                for (int mt = 0; mt < 2; mt++) LDSM4(ah[mt], base + aRowOff + mt * 2048 + ka);
                #pragma unroll
                for (int np = 0; np < 2; np++) {
                    uint32_t t4[4];
                    LDSM4(t4, base + TILE_B + bRowOff + np * 2048 + kb);
                    bh[2 * np][0] = t4[0]; bh[2 * np][1] = t4[1];
                    bh[2 * np + 1][0] = t4[2]; bh[2 * np + 1][1] = t4[3];
                }
                #pragma unroll
                for (int mt = 0; mt < 2; mt++)
                    #pragma unroll
                    for (int nt = 0; nt < 4; nt++)
                        MMA_F16(c[mt][nt], ah[mt], bh[nt][0], bh[nt][1]);
            } else {
                const uint32_t bAh = base, bAl = base + TILE_B;
                const uint32_t bBh = base + 2 * TILE_B, bBl = base + 3 * TILE_B;
                uint32_t ah[2][4], al[2][4], bh[4][2], bl[4][2];
                #pragma unroll
                for (int mt = 0; mt < 2; mt++) LDSM4(ah[mt], bAh + aRowOff + mt * 2048 + ka);
                #pragma unroll
                for (int mt = 0; mt < 2; mt++) LDSM4(al[mt], bAl + aRowOff + mt * 2048 + ka);
                #pragma unroll
                for (int np = 0; np < 2; np++) {
                    uint32_t t4[4];
                    LDSM4(t4, bBh + bRowOff + np * 2048 + kb);
                    bh[2 * np][0] = t4[0]; bh[2 * np][1] = t4[1];
                    bh[2 * np + 1][0] = t4[2]; bh[2 * np + 1][1] = t4[3];
                    LDSM4(t4, bBl + bRowOff + np * 2048 + kb);
                    bl[2 * np][0] = t4[0]; bl[2 * np][1] = t4[1];
                    bl[2 * np + 1][0] = t4[2]; bl[2 * np + 1][1] = t4[3];
                }
                #pragma unroll
                for (int mt = 0; mt < 2; mt++)
                    #pragma unroll
                    for (int nt = 0; nt < 4; nt++) {
                        MMA_BF16(c[mt][nt], ah[mt], bh[nt][0], bh[nt][1]);
                        MMA_BF16(c[mt][nt], ah[mt], bl[nt][0], bl[nt][1]);
                        MMA_BF16(c[mt][nt], al[mt], bh[nt][0], bh[nt][1]);
                    }
            }
        }
    };

    load_chunk(0, 0);
    load_chunk(1, 1);

    for (int i = 0; i < nchunks; i++) {
        const int s = i & 1;
        cp_wait1();
        __syncthreads();
        compute(s);
        __syncthreads();
        if (i + 2 < nchunks) load_chunk(s, i + 2);
        else cp_commit();
    }

    // Epilogue: C frag -> global. thread: rows g, g+8; col pair 2t.
    const int g = lane >> 2, t = lane & 3;
    #pragma unroll
    for (int mt = 0; mt < 2; mt++) {
        #pragma unroll
        for (int nt = 0; nt < 4; nt++) {
            const int col = bx * 128 + n0 + nt * 8 + t * 2;
            #pragma unroll
            for (int h = 0; h < 2; h++) {
                const int row = by * 128 + m0 + mt * 16 + g + h * 8;
                float v0 = c[mt][nt][2 * h + 0];
                float v1 = c[mt][nt][2 * h + 1];
                if (MODE == 0 || MODE == 1) { v0 += bias[col]; v1 += bias[col + 1]; }
                if (MODE == 2) { v0 *= scale; v1 *= scale; }
                const size_t o = (size_t)row * Nld + col;
                if (MODE == 0) {
                    *(__half2*)(Chf + o) = __floats2half2_rn(v0, v1);
                } else {
                    *(float2*)(Cf + o) = make_float2(v0, v1);
                }
            }
        }
    }
}

// ---------------------------------------------------------------------------
// fp32 -> bf16 hi/lo split (elementwise)
// ---------------------------------------------------------------------------
__global__ __launch_bounds__(256) void split_f32(const float* __restrict__ in,
                                                 __nv_bfloat16* __restrict__ hi,
                                                 __nv_bfloat16* __restrict__ lo, int n4)
{
    int i = blockIdx.x * 256 + threadIdx.x;
    if (i >= n4) return;
    float4 v = ((const float4*)in)[i];
    __nv_bfloat16 h[4], l[4];
    float f[4] = {v.x, v.y, v.z, v.w};
    #pragma unroll
    for (int k = 0; k < 4; k++) {
        h[k] = __float2bfloat16(f[k]);
        l[k] = __float2bfloat16(f[k] - __bfloat162float(h[k]));
    }
    ((__nv_bfloat162*)hi)[i * 2]     = __nv_bfloat162(h[0], h[1]);
    ((__nv_bfloat162*)hi)[i * 2 + 1] = __nv_bfloat162(h[2], h[3]);
    ((__nv_bfloat162*)lo)[i * 2]     = __nv_bfloat162(l[0], l[1]);
    ((__nv_bfloat162*)lo)[i * 2 + 1] = __nv_bfloat162(l[2], l[3]);
}

// ---------------------------------------------------------------------------
// V [SEQ, DIM] -> Vt fp16 [DIM, SEQ] (transpose + convert)
// ---------------------------------------------------------------------------
__global__ __launch_bounds__(256) void transpose_half(const float* __restrict__ V,
                                                      __half* __restrict__ Vtf)
{
    __shared__ float t[32][33];
    const int x0 = blockIdx.x * 32;
    const int y0 = blockIdx.y * 32;
    const int tx = threadIdx.x & 31, ty = threadIdx.x >> 5;
    #pragma unroll
    for (int i = 0; i < 32; i += 8)
        t[ty + i][tx] = V[(size_t)(y0 + ty + i) * DIM + x0 + tx];
    __syncthreads();
    #pragma unroll
    for (int i = 0; i < 32; i += 8) {
        float v = t[tx][ty + i];
        Vtf[(size_t)(x0 + ty + i) * SEQ + y0 + tx] = __float2half_rn(v);
    }
}

// ---------------------------------------------------------------------------
// In-place causal softmax; emits attn fp16 for the AV GEMM.
// fp16 zero-fill only to the next 128 boundary (AV truncates K there);
// fp32 upper triangle zeroed fully (required output).
// ---------------------------------------------------------------------------
__global__ __launch_bounds__(256) void softmax_causal(float* __restrict__ attn,
                                                      __half* __restrict__ af)
{
    extern __shared__ float row[];
    __shared__ float red[33];

    const int i = blockIdx.x;
    const int n = i + 1;
    const int tid = threadIdx.x;
    float* p = attn + (size_t)i * SEQ;
    __half* pf = af + (size_t)i * SEQ;

    float m = -1e30f;
    for (int j = tid; j < n; j += 256) {
        float v = p[j];
        row[j] = v;
        m = fmaxf(m, v);
    }
    #pragma unroll
    for (int o = 16; o; o >>= 1) m = fmaxf(m, __shfl_xor_sync(0xffffffffu, m, o));
    if ((tid & 31) == 0) red[tid >> 5] = m;
    __syncthreads();
    if (tid < 32) {
        float v = (tid < 8) ? red[tid] : -1e30f;
        #pragma unroll
        for (int o = 4; o; o >>= 1) v = fmaxf(v, __shfl_xor_sync(0xffffffffu, v, o));
        if (tid == 0) red[32] = v;
    }
    __syncthreads();
    const float rowmax = red[32];
    __syncthreads();

    float s = 0.0f;
    for (int j = tid; j < n; j += 256) {
        float e = __expf(row[j] - rowmax);
        row[j] = e;
        s += e;
    }
    #pragma unroll
    for (int o = 16; o; o >>= 1) s += __shfl_xor_sync(0xffffffffu, s, o);
    if ((tid & 31) == 0) red[tid >> 5] = s;
    __syncthreads();
    if (tid < 32) {
        float v = (tid < 8) ? red[tid] : 0.0f;
        #pragma unroll
        for (int o = 4; o; o >>= 1) v += __shfl_xor_sync(0xffffffffu, v, o);
        if (tid == 0) red[32] = v;
    }
    __syncthreads();
    const float inv = 1.0f / red[32];

    for (int j = tid; j < n; j += 256) {
        float v = row[j] * inv;
        p[j] = v;
        pf[j] = __float2half_rn(v);
    }
    const int nend = (n + 127) & ~127;            // AV never reads past this
    const __half z = __float2half_rn(0.0f);
    for (int j = n + tid; j < nend; j += 256) pf[j] = z;
    for (int j = n + tid; j < SEQ; j += 256) p[j] = 0.0f;
}

// ---------------------------------------------------------------------------
extern "C" void kernel_launch(void* const* d_in, const int* in_sizes, int n_in,
                              void* d_out, int out_size)
{
    const float* x  = (const float*)d_in[0];
    const float* Wq = (const float*)d_in[1];
    const float* bq = (const float*)d_in[2];
    const float* Wk = (const float*)d_in[3];
    const float* bk = (const float*)d_in[4];
    const float* Wv = (const float*)d_in[5];
    const float* bv = (const float*)d_in[6];

    float* out  = (float*)d_out;                 // [SEQ, DIM]
    float* attn = out + (size_t)SEQ * DIM;       // [SEQ, SEQ]

    __nv_bfloat16 *xh, *xl, *Wqh, *Wql, *Wkh, *Wkl, *Wvh, *Wvl;
    __half *Qf, *Kf, *Vtf, *Af;
    float* Vf;
    cudaGetSymbolAddress((void**)&xh, g_xh);   cudaGetSymbolAddress((void**)&xl, g_xl);
    cudaGetSymbolAddress((void**)&Wqh, g_Wqh); cudaGetSymbolAddress((void**)&Wql, g_Wql);
    cudaGetSymbolAddress((void**)&Wkh, g_Wkh); cudaGetSymbolAddress((void**)&Wkl, g_Wkl);
    cudaGetSymbolAddress((void**)&Wvh, g_Wvh); cudaGetSymbolAddress((void**)&Wvl, g_Wvl);
    cudaGetSymbolAddress((void**)&Qf, g_Qf);   cudaGetSymbolAddress((void**)&Kf, g_Kf);
    cudaGetSymbolAddress((void**)&Vtf, g_Vtf); cudaGetSymbolAddress((void**)&Af, g_Af);
    cudaGetSymbolAddress((void**)&Vf, g_V);

    cudaFuncSetAttribute(mma_gemm<0>, cudaFuncAttributeMaxDynamicSharedMemorySize, GEMM_SMEM);
    cudaFuncSetAttribute(mma_gemm<1>, cudaFuncAttributeMaxDynamicSharedMemorySize, GEMM_SMEM);
    cudaFuncSetAttribute(mma_gemm<2>, cudaFuncAttributeMaxDynamicSharedMemorySize, GEMM_SMEM);
    cudaFuncSetAttribute(mma_gemm<3>, cudaFuncAttributeMaxDynamicSharedMemorySize, GEMM_SMEM);

    const float inv_sqrt_d = 0.04419417382415922f;  // 1/sqrt(512)

    // 1) split inputs to bf16 hi/lo
    split_f32<<<(SEQ * DIM / 4 + 255) / 256, 256>>>(x, xh, xl, SEQ * DIM / 4);
    split_f32<<<(DIM * DIM / 4 + 255) / 256, 256>>>(Wq, Wqh, Wql, DIM * DIM / 4);
    split_f32<<<(DIM * DIM / 4 + 255) / 256, 256>>>(Wk, Wkh, Wkl, DIM * DIM / 4);
    split_f32<<<(DIM * DIM / 4 + 255) / 256, 256>>>(Wv, Wvh, Wvl, DIM * DIM / 4);

    // 2) QKV projections (3-term bf16 mma.sync); Q,K -> fp16, V -> fp32
    dim3 gqkv(DIM / 128, SEQ / 128);
    mma_gemm<0><<<gqkv, 512, GEMM_SMEM>>>(xh, xl, Wqh, Wql, bq, nullptr, Qf, DIM, DIM, 1.0f);
    mma_gemm<0><<<gqkv, 512, GEMM_SMEM>>>(xh, xl, Wkh, Wkl, bk, nullptr, Kf, DIM, DIM, 1.0f);
    mma_gemm<1><<<gqkv, 512, GEMM_SMEM>>>(xh, xl, Wvh, Wvl, bv, Vf, nullptr, DIM, DIM, 1.0f);

    // 3) V -> Vt fp16
    transpose_half<<<dim3(DIM / 32, SEQ / 32), 256>>>(Vf, Vtf);

    // 4) scores = (Q @ K^T) * inv_sqrt_d (single-term fp16, lower-triangle tiles)
    dim3 gsc(SEQ / 128, SEQ / 128);
    mma_gemm<2><<<gsc, 512, GEMM_SMEM>>>((const __nv_bfloat16*)Qf, nullptr,
                                         (const __nv_bfloat16*)Kf, nullptr,
                                         nullptr, attn, nullptr, SEQ, DIM, inv_sqrt_d);

    // 5) causal softmax (fp32 out + fp16 attn for AV)
    softmax_causal<<<SEQ, 256, SEQ * sizeof(float)>>>(attn, Af);

    // 6) out = attn @ V  (single-term fp16, K truncated per row-block)
    dim3 gav(DIM / 128, SEQ / 128);
    mma_gemm<3><<<gav, 512, GEMM_SMEM>>>((const __nv_bfloat16*)Af, nullptr,
                                         (const __nv_bfloat16*)Vtf, nullptr,
                                         nullptr, out, nullptr, DIM, SEQ, 1.0f);
}

// round 15
// speedup vs baseline: 2.0644x; 1.1556x over previous
#include <cuda_runtime.h>
#include <cuda_bf16.h>
#include <cuda_fp16.h>
#include <math.h>
#include <stdint.h>

#define SEQ 8192
#define DIM 512

// ---------------------------------------------------------------------------
// Scratch (allocation-free rule: __device__ globals)
// ---------------------------------------------------------------------------
__device__ __half        g_xf[SEQ * DIM];
__device__ __nv_bfloat16 g_xh[SEQ * DIM], g_xl[SEQ * DIM];
__device__ __half        g_Wqf[DIM * DIM], g_Wkf[DIM * DIM];
__device__ __nv_bfloat16 g_Wvh[DIM * DIM], g_Wvl[DIM * DIM];
__device__ __half        g_Qf[SEQ * DIM];
__device__ __half        g_Kf[SEQ * DIM];
__device__ float         g_V[SEQ * DIM];
__device__ __half        g_Vtf[DIM * SEQ];
__device__ __half        g_Af[(size_t)SEQ * SEQ];

// ---------------------------------------------------------------------------
// PTX helpers (baseline ISA only — tcgen05 unavailable on this toolchain)
// ---------------------------------------------------------------------------
__device__ __forceinline__ uint32_t smem_u32(const void* p) {
    uint32_t a;
    asm("{ .reg .u64 t; cvta.to.shared.u64 t, %1; cvt.u32.u64 %0, t; }" : "=r"(a) : "l"(p));
    return a;
}
__device__ __forceinline__ void cp16(uint32_t dst, const void* src) {
    asm volatile("cp.async.cg.shared.global [%0], [%1], 16;" :: "r"(dst), "l"(src) : "memory");
}
__device__ __forceinline__ void cp_commit() { asm volatile("cp.async.commit_group;" ::: "memory"); }
__device__ __forceinline__ void cp_wait1()  { asm volatile("cp.async.wait_group 1;"  ::: "memory"); }

#define SW128(o) ((o) ^ (((o) >> 3) & 0x70))

#define LDSM4(r, a)                                                              \
    asm volatile("ldmatrix.sync.aligned.m8n8.x4.shared.b16 {%0,%1,%2,%3}, [%4];" \
        : "=r"((r)[0]), "=r"((r)[1]), "=r"((r)[2]), "=r"((r)[3]) : "r"(a))

#define MMA_BF16(c, a, b0, b1)                                                   \
    asm volatile("mma.sync.aligned.m16n8k16.row.col.f32.bf16.bf16.f32 "          \
        "{%0,%1,%2,%3}, {%4,%5,%6,%7}, {%8,%9}, {%0,%1,%2,%3};"                  \
        : "+f"((c)[0]), "+f"((c)[1]), "+f"((c)[2]), "+f"((c)[3])                 \
        : "r"((a)[0]), "r"((a)[1]), "r"((a)[2]), "r"((a)[3]), "r"(b0), "r"(b1))

#define MMA_F16(c, a, b0, b1)                                                    \
    asm volatile("mma.sync.aligned.m16n8k16.row.col.f32.f16.f16.f32 "            \
        "{%0,%1,%2,%3}, {%4,%5,%6,%7}, {%8,%9}, {%0,%1,%2,%3};"                  \
        : "+f"((c)[0]), "+f"((c)[1]), "+f"((c)[2]), "+f"((c)[3])                 \
        : "r"((a)[0]), "r"((a)[1]), "r"((a)[2]), "r"((a)[3]), "r"(b0), "r"(b1))

// ---------------------------------------------------------------------------
// HMMA NT GEMM.
// MODE 0 = proj QK  single-term fp16, bias, fp16 output Chf
// MODE 1 = proj V   3-term bf16 split, bias, fp32 output Cf
// MODE 2 = scores   single-term fp16, causal tile skip, scale, fp32 output
// MODE 3 = AV       single-term fp16, K truncated, fp32 output, heavy-first
// BM=BN=128, BK=64 (128B rows, SW128). 512 threads, 16 warps x (32x32 tile).
// 2-stage cp.async double buffer. Tiles/chunk: 4 (mode 1) or 2 (others).
// ---------------------------------------------------------------------------
#define TILE_B 16384
#define GEMM_SMEM (8 * TILE_B + 1024)

template<int MODE>
__global__ __launch_bounds__(512) void mma_gemm(
    const __nv_bfloat16* __restrict__ Ah, const __nv_bfloat16* __restrict__ Al,
    const __nv_bfloat16* __restrict__ Bh, const __nv_bfloat16* __restrict__ Bl,
    const float* __restrict__ bias,
    float* __restrict__ Cf, __half* __restrict__ Chf,
    int Nld, int Kd, float scale)
{
    constexpr int NT = (MODE == 1) ? 4 : 2;   // tiles per chunk
    const int bx = blockIdx.x;
    // AV: heavy row-blocks first (work per CTA ~ by+1)
    const int by = (MODE == 3) ? (gridDim.y - 1 - blockIdx.y) : blockIdx.y;
    if (MODE == 2 && bx > by) return;

    extern __shared__ char dsm[];
    uint32_t sb = smem_u32(dsm);
    sb = (sb + 1023) & ~1023u;

    const int tid  = threadIdx.x;
    const int wid  = tid >> 5;
    const int lane = tid & 31;
    const int m0   = (wid >> 2) * 32;   // warp M origin (0,32,64,96)
    const int n0   = (wid & 3) * 32;    // warp N origin (0,32,64,96)

    const int kmax    = (MODE == 3) ? (by + 1) * 128 : Kd;
    const int nchunks = kmax >> 6;      // >= 2 always

    const __nv_bfloat16* P[NT];
    if (MODE == 1) {
        P[0] = Ah + (size_t)by * 128 * Kd;
        P[1] = Al + (size_t)by * 128 * Kd;
        P[2] = Bh + (size_t)bx * 128 * Kd;
        P[3] = Bl + (size_t)bx * 128 * Kd;
    } else {
        P[0] = Ah + (size_t)by * 128 * Kd;   // fp16 data (reinterpreted)
        P[1] = Bh + (size_t)bx * 128 * Kd;
    }

    // loader: NT tiles x 128 rows x 8 segs(16B) per chunk
    auto load_chunk = [&](int s, int chunk) {
        const uint32_t stage_base = sb + s * NT * TILE_B;
        #pragma unroll
        for (int i = 0; i < 2; i++) {
            int idx = tid + i * 512;       // 0..1023
            int row = idx >> 3;
            int seg = idx & 7;
            uint32_t so = SW128((uint32_t)(row * 128 + seg * 16));
            #pragma unroll
            for (int t = 0; t < NT; t++) {
                const __nv_bfloat16* src = P[t] + (size_t)row * Kd + chunk * 64 + seg * 8;
                cp16(stage_base + t * TILE_B + so, src);
            }
        }
        cp_commit();
    };

    float c[2][4][4] = {};

    // ldmatrix lane addressing (SW128: XOR (row&7)<<4 into the 16B-seg bits)
    const int la = lane & 15;                       // A: rows 0..15
    const int sa = lane >> 4;                       // A: k-seg select
    const int lb = (lane & 7) | ((lane >> 4) << 3); // B: rows 0..7 / 8..15
    const int sbg = (lane >> 3) & 1;                // B: k-seg select
    const uint32_t xa = (uint32_t)(lane & 7) << 4;
    const uint32_t aRowOff = (uint32_t)(m0 + la) * 128;
    const uint32_t bRowOff = (uint32_t)(n0 + lb) * 128;

    auto compute = [&](int s) {
        const uint32_t base = sb + s * NT * TILE_B;
        #pragma unroll
        for (int ks = 0; ks < 4; ks++) {
            const uint32_t ka = ((uint32_t)(ks * 32 + sa * 16)) ^ xa;
            const uint32_t kb = ((uint32_t)(ks * 32 + sbg * 16)) ^ xa;
            if (MODE != 1) {
                // single fp16 term: A tile at base, B tile at base+TILE_B
                uint32_t ah[2][4], bh[4][2];
                #pragma unroll
                for (int mt = 0; mt < 2; mt++) LDSM4(ah[mt], base + aRowOff + mt * 2048 + ka);
                #pragma unroll
                for (int np = 0; np < 2; np++) {
                    uint32_t t4[4];
                    LDSM4(t4, base + TILE_B + bRowOff + np * 2048 + kb);
                    bh[2 * np][0] = t4[0]; bh[2 * np][1] = t4[1];
                    bh[2 * np + 1][0] = t4[2]; bh[2 * np + 1][1] = t4[3];
                }
                #pragma unroll
                for (int mt = 0; mt < 2; mt++)
                    #pragma unroll
                    for (int nt = 0; nt < 4; nt++)
                        MMA_F16(c[mt][nt], ah[mt], bh[nt][0], bh[nt][1]);
            } else {
                const uint32_t bAh = base, bAl = base + TILE_B;
                const uint32_t bBh = base + 2 * TILE_B, bBl = base + 3 * TILE_B;
                uint32_t ah[2][4], al[2][4], bh[4][2], bl[4][2];
                #pragma unroll
                for (int mt = 0; mt < 2; mt++) LDSM4(ah[mt], bAh + aRowOff + mt * 2048 + ka);
                #pragma unroll
                for (int mt = 0; mt < 2; mt++) LDSM4(al[mt], bAl + aRowOff + mt * 2048 + ka);
                #pragma unroll
                for (int np = 0; np < 2; np++) {
                    uint32_t t4[4];
                    LDSM4(t4, bBh + bRowOff + np * 2048 + kb);
                    bh[2 * np][0] = t4[0]; bh[2 * np][1] = t4[1];
                    bh[2 * np + 1][0] = t4[2]; bh[2 * np + 1][1] = t4[3];
                    LDSM4(t4, bBl + bRowOff + np * 2048 + kb);
                    bl[2 * np][0] = t4[0]; bl[2 * np][1] = t4[1];
                    bl[2 * np + 1][0] = t4[2]; bl[2 * np + 1][1] = t4[3];
                }
                #pragma unroll
                for (int mt = 0; mt < 2; mt++)
                    #pragma unroll
                    for (int nt = 0; nt < 4; nt++) {
                        MMA_BF16(c[mt][nt], ah[mt], bh[nt][0], bh[nt][1]);
                        MMA_BF16(c[mt][nt], ah[mt], bl[nt][0], bl[nt][1]);
                        MMA_BF16(c[mt][nt], al[mt], bh[nt][0], bh[nt][1]);
                    }
            }
        }
    };

    load_chunk(0, 0);
    load_chunk(1, 1);

    for (int i = 0; i < nchunks; i++) {
        const int s = i & 1;
        cp_wait1();
        __syncthreads();
        compute(s);
        __syncthreads();
        if (i + 2 < nchunks) load_chunk(s, i + 2);
        else cp_commit();
    }

    // Epilogue: C frag -> global. thread: rows g, g+8; col pair 2t.
    const int g = lane >> 2, t = lane & 3;
    #pragma unroll
    for (int mt = 0; mt < 2; mt++) {
        #pragma unroll
        for (int nt = 0; nt < 4; nt++) {
            const int col = bx * 128 + n0 + nt * 8 + t * 2;
            #pragma unroll
            for (int h = 0; h < 2; h++) {
                const int row = by * 128 + m0 + mt * 16 + g + h * 8;
                float v0 = c[mt][nt][2 * h + 0];
                float v1 = c[mt][nt][2 * h + 1];
                if (MODE == 0 || MODE == 1) { v0 += bias[col]; v1 += bias[col + 1]; }
                if (MODE == 2) { v0 *= scale; v1 *= scale; }
                const size_t o = (size_t)row * Nld + col;
                if (MODE == 0) {
                    *(__half2*)(Chf + o) = __floats2half2_rn(v0, v1);
                } else {
                    *(float2*)(Cf + o) = make_float2(v0, v1);
                }
            }
        }
    }
}

// ---------------------------------------------------------------------------
// fp32 -> bf16 hi/lo split (elementwise)
// ---------------------------------------------------------------------------
__global__ __launch_bounds__(256) void split_f32(const float* __restrict__ in,
                                                 __nv_bfloat16* __restrict__ hi,
                                                 __nv_bfloat16* __restrict__ lo, int n4)
{
    int i = blockIdx.x * 256 + threadIdx.x;
    if (i >= n4) return;
    float4 v = ((const float4*)in)[i];
    __nv_bfloat16 h[4], l[4];
    float f[4] = {v.x, v.y, v.z, v.w};
    #pragma unroll
    for (int k = 0; k < 4; k++) {
        h[k] = __float2bfloat16(f[k]);
        l[k] = __float2bfloat16(f[k] - __bfloat162float(h[k]));
    }
    ((__nv_bfloat162*)hi)[i * 2]     = __nv_bfloat162(h[0], h[1]);
    ((__nv_bfloat162*)hi)[i * 2 + 1] = __nv_bfloat162(h[2], h[3]);
    ((__nv_bfloat162*)lo)[i * 2]     = __nv_bfloat162(l[0], l[1]);
    ((__nv_bfloat162*)lo)[i * 2 + 1] = __nv_bfloat162(l[2], l[3]);
}

// ---------------------------------------------------------------------------
// fp32 -> fp16 convert (elementwise)
// ---------------------------------------------------------------------------
__global__ __launch_bounds__(256) void convert_half(const float* __restrict__ in,
                                                    __half* __restrict__ out, int n4)
{
    int i = blockIdx.x * 256 + threadIdx.x;
    if (i >= n4) return;
    float4 v = ((const float4*)in)[i];
    ((__half2*)out)[i * 2]     = __floats2half2_rn(v.x, v.y);
    ((__half2*)out)[i * 2 + 1] = __floats2half2_rn(v.z, v.w);
}

// ---------------------------------------------------------------------------
// V [SEQ, DIM] -> Vt fp16 [DIM, SEQ] (transpose + convert)
// ---------------------------------------------------------------------------
__global__ __launch_bounds__(256) void transpose_half(const float* __restrict__ V,
                                                      __half* __restrict__ Vtf)
{
    __shared__ float t[32][33];
    const int x0 = blockIdx.x * 32;
    const int y0 = blockIdx.y * 32;
    const int tx = threadIdx.x & 31, ty = threadIdx.x >> 5;
    #pragma unroll
    for (int i = 0; i < 32; i += 8)
        t[ty + i][tx] = V[(size_t)(y0 + ty + i) * DIM + x0 + tx];
    __syncthreads();
    #pragma unroll
    for (int i = 0; i < 32; i += 8) {
        float v = t[tx][ty + i];
        Vtf[(size_t)(x0 + ty + i) * SEQ + y0 + tx] = __float2half_rn(v);
    }
}

// ---------------------------------------------------------------------------
// In-place causal softmax; emits attn fp16 for the AV GEMM.
// fp16 zero-fill only to the next 128 boundary (AV truncates K there);
// fp32 upper triangle zeroed fully (required output).
// ---------------------------------------------------------------------------
__global__ __launch_bounds__(256) void softmax_causal(float* __restrict__ attn,
                                                      __half* __restrict__ af)
{
    extern __shared__ float row[];
    __shared__ float red[33];

    const int i = blockIdx.x;
    const int n = i + 1;
    const int tid = threadIdx.x;
    float* p = attn + (size_t)i * SEQ;
    __half* pf = af + (size_t)i * SEQ;

    float m = -1e30f;
    for (int j = tid; j < n; j += 256) {
        float v = p[j];
        row[j] = v;
        m = fmaxf(m, v);
    }
    #pragma unroll
    for (int o = 16; o; o >>= 1) m = fmaxf(m, __shfl_xor_sync(0xffffffffu, m, o));
    if ((tid & 31) == 0) red[tid >> 5] = m;
    __syncthreads();
    if (tid < 32) {
        float v = (tid < 8) ? red[tid] : -1e30f;
        #pragma unroll
        for (int o = 4; o; o >>= 1) v = fmaxf(v, __shfl_xor_sync(0xffffffffu, v, o));
        if (tid == 0) red[32] = v;
    }
    __syncthreads();
    const float rowmax = red[32];
    __syncthreads();

    float s = 0.0f;
    for (int j = tid; j < n; j += 256) {
        float e = __expf(row[j] - rowmax);
        row[j] = e;
        s += e;
    }
    #pragma unroll
    for (int o = 16; o; o >>= 1) s += __shfl_xor_sync(0xffffffffu, s, o);
    if ((tid & 31) == 0) red[tid >> 5] = s;
    __syncthreads();
    if (tid < 32) {
        float v = (tid < 8) ? red[tid] : 0.0f;
        #pragma unroll
        for (int o = 4; o; o >>= 1) v += __shfl_xor_sync(0xffffffffu, v, o);
        if (tid == 0) red[32] = v;
    }
    __syncthreads();
    const float inv = 1.0f / red[32];

    for (int j = tid; j < n; j += 256) {
        float v = row[j] * inv;
        p[j] = v;
        pf[j] = __float2half_rn(v);
    }
    const int nend = (n + 127) & ~127;            // AV never reads past this
    const __half z = __float2half_rn(0.0f);
    for (int j = n + tid; j < nend; j += 256) pf[j] = z;
    for (int j = n + tid; j < SEQ; j += 256) p[j] = 0.0f;
}

// ---------------------------------------------------------------------------
extern "C" void kernel_launch(void* const* d_in, const int* in_sizes, int n_in,
                              void* d_out, int out_size)
{
    const float* x  = (const float*)d_in[0];
    const float* Wq = (const float*)d_in[1];
    const float* bq = (const float*)d_in[2];
    const float* Wk = (const float*)d_in[3];
    const float* bk = (const float*)d_in[4];
    const float* Wv = (const float*)d_in[5];
    const float* bv = (const float*)d_in[6];

    float* out  = (float*)d_out;                 // [SEQ, DIM]
    float* attn = out + (size_t)SEQ * DIM;       // [SEQ, SEQ]

    __nv_bfloat16 *xh, *xl, *Wvh, *Wvl;
    __half *xf, *Wqf, *Wkf, *Qf, *Kf, *Vtf, *Af;
    float* Vf;
    cudaGetSymbolAddress((void**)&xf, g_xf);
    cudaGetSymbolAddress((void**)&xh, g_xh);   cudaGetSymbolAddress((void**)&xl, g_xl);
    cudaGetSymbolAddress((void**)&Wqf, g_Wqf); cudaGetSymbolAddress((void**)&Wkf, g_Wkf);
    cudaGetSymbolAddress((void**)&Wvh, g_Wvh); cudaGetSymbolAddress((void**)&Wvl, g_Wvl);
    cudaGetSymbolAddress((void**)&Qf, g_Qf);   cudaGetSymbolAddress((void**)&Kf, g_Kf);
    cudaGetSymbolAddress((void**)&Vtf, g_Vtf); cudaGetSymbolAddress((void**)&Af, g_Af);
    cudaGetSymbolAddress((void**)&Vf, g_V);

    cudaFuncSetAttribute(mma_gemm<0>, cudaFuncAttributeMaxDynamicSharedMemorySize, GEMM_SMEM);
    cudaFuncSetAttribute(mma_gemm<1>, cudaFuncAttributeMaxDynamicSharedMemorySize, GEMM_SMEM);
    cudaFuncSetAttribute(mma_gemm<2>, cudaFuncAttributeMaxDynamicSharedMemorySize, GEMM_SMEM);
    cudaFuncSetAttribute(mma_gemm<3>, cudaFuncAttributeMaxDynamicSharedMemorySize, GEMM_SMEM);

    const float inv_sqrt_d = 0.04419417382415922f;  // 1/sqrt(512)

    // 1) input conversions
    convert_half<<<(SEQ * DIM / 4 + 255) / 256, 256>>>(x, xf, SEQ * DIM / 4);
    convert_half<<<(DIM * DIM / 4 + 255) / 256, 256>>>(Wq, Wqf, DIM * DIM / 4);
    convert_half<<<(DIM * DIM / 4 + 255) / 256, 256>>>(Wk, Wkf, DIM * DIM / 4);
    split_f32<<<(SEQ * DIM / 4 + 255) / 256, 256>>>(x, xh, xl, SEQ * DIM / 4);
    split_f32<<<(DIM * DIM / 4 + 255) / 256, 256>>>(Wv, Wvh, Wvl, DIM * DIM / 4);

    // 2) projections: Q,K single-term fp16 -> fp16; V 3-term bf16 -> fp32
    dim3 gqkv(DIM / 128, SEQ / 128);
    mma_gemm<0><<<gqkv, 512, GEMM_SMEM>>>((const __nv_bfloat16*)xf, nullptr,
                                          (const __nv_bfloat16*)Wqf, nullptr,
                                          bq, nullptr, Qf, DIM, DIM, 1.0f);
    mma_gemm<0><<<gqkv, 512, GEMM_SMEM>>>((const __nv_bfloat16*)xf, nullptr,
                                          (const __nv_bfloat16*)Wkf, nullptr,
                                          bk, nullptr, Kf, DIM, DIM, 1.0f);
    mma_gemm<1><<<gqkv, 512, GEMM_SMEM>>>(xh, xl, Wvh, Wvl, bv, Vf, nullptr, DIM, DIM, 1.0f);

    // 3) V -> Vt fp16
    transpose_half<<<dim3(DIM / 32, SEQ / 32), 256>>>(Vf, Vtf);

    // 4) scores = (Q @ K^T) * inv_sqrt_d (single-term fp16, lower-triangle tiles)
    dim3 gsc(SEQ / 128, SEQ / 128);
    mma_gemm<2><<<gsc, 512, GEMM_SMEM>>>((const __nv_bfloat16*)Qf, nullptr,
                                         (const __nv_bfloat16*)Kf, nullptr,
                                         nullptr, attn, nullptr, SEQ, DIM, inv_sqrt_d);

    // 5) causal softmax (fp32 out + fp16 attn for AV)
    softmax_causal<<<SEQ, 256, SEQ * sizeof(float)>>>(attn, Af);

    // 6) out = attn @ V  (single-term fp16, K truncated, heavy-first)
    dim3 gav(DIM / 128, SEQ / 128);
    mma_gemm<3><<<gav, 512, GEMM_SMEM>>>((const __nv_bfloat16*)Af, nullptr,
                                         (const __nv_bfloat16*)Vtf, nullptr,
                                         nullptr, out, nullptr, DIM, SEQ, 1.0f);
}

// round 16
// speedup vs baseline: 2.2713x; 1.1002x over previous
#include <cuda_runtime.h>
#include <cuda_fp16.h>
#include <math.h>
#include <stdint.h>

#define SEQ 8192
#define DIM 512

// ---------------------------------------------------------------------------
// Scratch (allocation-free rule: __device__ globals) — all fp16 now
// ---------------------------------------------------------------------------
__device__ __half g_xf[SEQ * DIM];
__device__ __half g_Wqf[DIM * DIM], g_Wkf[DIM * DIM], g_Wvf[DIM * DIM];
__device__ __half g_Qf[SEQ * DIM], g_Kf[SEQ * DIM], g_Vf[SEQ * DIM];
__device__ __half g_Vtf[DIM * SEQ];
__device__ __half g_Af[(size_t)SEQ * SEQ];

// ---------------------------------------------------------------------------
// PTX helpers (baseline ISA only — tcgen05 unavailable on this toolchain)
// ---------------------------------------------------------------------------
__device__ __forceinline__ uint32_t smem_u32(const void* p) {
    uint32_t a;
    asm("{ .reg .u64 t; cvta.to.shared.u64 t, %1; cvt.u32.u64 %0, t; }" : "=r"(a) : "l"(p));
    return a;
}
__device__ __forceinline__ void cp16(uint32_t dst, const void* src) {
    asm volatile("cp.async.cg.shared.global [%0], [%1], 16;" :: "r"(dst), "l"(src) : "memory");
}
__device__ __forceinline__ void cp_commit() { asm volatile("cp.async.commit_group;" ::: "memory"); }
__device__ __forceinline__ void cp_wait1()  { asm volatile("cp.async.wait_group 1;"  ::: "memory"); }

#define SW128(o) ((o) ^ (((o) >> 3) & 0x70))

#define LDSM4(r, a)                                                              \
    asm volatile("ldmatrix.sync.aligned.m8n8.x4.shared.b16 {%0,%1,%2,%3}, [%4];" \
        : "=r"((r)[0]), "=r"((r)[1]), "=r"((r)[2]), "=r"((r)[3]) : "r"(a))

#define MMA_F16(c, a, b0, b1)                                                    \
    asm volatile("mma.sync.aligned.m16n8k16.row.col.f32.f16.f16.f32 "            \
        "{%0,%1,%2,%3}, {%4,%5,%6,%7}, {%8,%9}, {%0,%1,%2,%3};"                  \
        : "+f"((c)[0]), "+f"((c)[1]), "+f"((c)[2]), "+f"((c)[3])                 \
        : "r"((a)[0]), "r"((a)[1]), "r"((a)[2]), "r"((a)[3]), "r"(b0), "r"(b1))

// ---------------------------------------------------------------------------
// Single-term fp16 HMMA NT GEMM: C[M,N] = A[M,Kd] @ B[N,Kd]^T
// MODE 0 = proj    bias, fp16 output Chf
// MODE 2 = scores  upper tiles (bx>by): pure fp32 zero-store; else scale, fp32
// MODE 3 = AV      K truncated to (by+1)*128, fp32 output, heavy-first order
// BM=BN=128, BK=64 (128B rows, SW128). 512 threads, 16 warps x (32x32 tile).
// 2-stage cp.async double buffer: 2 stages x 2 tiles x 16KB = 64KB smem.
// ---------------------------------------------------------------------------
#define TILE_B 16384
#define GEMM_SMEM (4 * TILE_B + 1024)

template<int MODE>
__global__ __launch_bounds__(512) void mma_gemm(
    const __half* __restrict__ A, const __half* __restrict__ B,
    const float* __restrict__ bias,
    float* __restrict__ Cf, __half* __restrict__ Chf,
    int Nld, int Kd, float scale)
{
    const int bx = blockIdx.x;
    const int by = (MODE == 3) ? (gridDim.y - 1 - blockIdx.y) : blockIdx.y;
    const int tid  = threadIdx.x;

    if (MODE == 2 && bx > by) {
        // strictly-upper tile: attn weights are exactly zero — store and exit
        float* dst = Cf + (size_t)by * 128 * Nld + bx * 128;
        const int w = tid >> 5, l = tid & 31;
        const float4 z4 = make_float4(0.f, 0.f, 0.f, 0.f);
        #pragma unroll
        for (int r = w; r < 128; r += 16)
            ((float4*)(dst + (size_t)r * Nld))[l] = z4;
        return;
    }

    extern __shared__ char dsm[];
    uint32_t sb = smem_u32(dsm);
    sb = (sb + 1023) & ~1023u;

    const int wid  = tid >> 5;
    const int lane = tid & 31;
    const int m0   = (wid >> 2) * 32;   // warp M origin (0,32,64,96)
    const int n0   = (wid & 3) * 32;    // warp N origin (0,32,64,96)

    const int kmax    = (MODE == 3) ? (by + 1) * 128 : Kd;
    const int nchunks = kmax >> 6;      // >= 2 always

    const __half* PA = A + (size_t)by * 128 * Kd;
    const __half* PB = B + (size_t)bx * 128 * Kd;

    // loader: 2 tiles x 128 rows x 8 segs(16B) per chunk
    auto load_chunk = [&](int s, int chunk) {
        const uint32_t stage_base = sb + s * 2 * TILE_B;
        #pragma unroll
        for (int i = 0; i < 2; i++) {
            int idx = tid + i * 512;       // 0..1023
            int row = idx >> 3;
            int seg = idx & 7;
            uint32_t so = SW128((uint32_t)(row * 128 + seg * 16));
            cp16(stage_base + so,          PA + (size_t)row * Kd + chunk * 64 + seg * 8);
            cp16(stage_base + TILE_B + so, PB + (size_t)row * Kd + chunk * 64 + seg * 8);
        }
        cp_commit();
    };

    float c[2][4][4] = {};

    // ldmatrix lane addressing (SW128: XOR (row&7)<<4 into the 16B-seg bits)
    const int la = lane & 15;                       // A: rows 0..15
    const int sa = lane >> 4;                       // A: k-seg select
    const int lb = (lane & 7) | ((lane >> 4) << 3); // B: rows 0..7 / 8..15
    const int sbg = (lane >> 3) & 1;                // B: k-seg select
    const uint32_t xa = (uint32_t)(lane & 7) << 4;
    const uint32_t aRowOff = (uint32_t)(m0 + la) * 128;
    const uint32_t bRowOff = (uint32_t)(n0 + lb) * 128;

    auto compute = [&](int s) {
        const uint32_t base = sb + s * 2 * TILE_B;
        #pragma unroll
        for (int ks = 0; ks < 4; ks++) {
            const uint32_t ka = ((uint32_t)(ks * 32 + sa * 16)) ^ xa;
            const uint32_t kb = ((uint32_t)(ks * 32 + sbg * 16)) ^ xa;
            uint32_t ah[2][4], bh[4][2];
            #pragma unroll
            for (int mt = 0; mt < 2; mt++) LDSM4(ah[mt], base + aRowOff + mt * 2048 + ka);
            #pragma unroll
            for (int np = 0; np < 2; np++) {
                uint32_t t4[4];
                LDSM4(t4, base + TILE_B + bRowOff + np * 2048 + kb);
                bh[2 * np][0] = t4[0]; bh[2 * np][1] = t4[1];
                bh[2 * np + 1][0] = t4[2]; bh[2 * np + 1][1] = t4[3];
            }
            #pragma unroll
            for (int mt = 0; mt < 2; mt++)
                #pragma unroll
                for (int nt = 0; nt < 4; nt++)
                    MMA_F16(c[mt][nt], ah[mt], bh[nt][0], bh[nt][1]);
        }
    };

    load_chunk(0, 0);
    load_chunk(1, 1);

    for (int i = 0; i < nchunks; i++) {
        const int s = i & 1;
        cp_wait1();
        __syncthreads();
        compute(s);
        __syncthreads();
        if (i + 2 < nchunks) load_chunk(s, i + 2);
        else cp_commit();
    }

    // Epilogue: C frag -> global. thread: rows g, g+8; col pair 2t.
    const int g = lane >> 2, t = lane & 3;
    #pragma unroll
    for (int mt = 0; mt < 2; mt++) {
        #pragma unroll
        for (int nt = 0; nt < 4; nt++) {
            const int col = bx * 128 + n0 + nt * 8 + t * 2;
            #pragma unroll
            for (int h = 0; h < 2; h++) {
                const int row = by * 128 + m0 + mt * 16 + g + h * 8;
                float v0 = c[mt][nt][2 * h + 0];
                float v1 = c[mt][nt][2 * h + 1];
                if (MODE == 0) { v0 += bias[col]; v1 += bias[col + 1]; }
                if (MODE == 2) { v0 *= scale; v1 *= scale; }
                const size_t o = (size_t)row * Nld + col;
                if (MODE == 0) {
                    *(__half2*)(Chf + o) = __floats2half2_rn(v0, v1);
                } else {
                    *(float2*)(Cf + o) = make_float2(v0, v1);
                }
            }
        }
    }
}

// ---------------------------------------------------------------------------
// fp32 -> fp16 convert (elementwise)
// ---------------------------------------------------------------------------
__global__ __launch_bounds__(256) void convert_half(const float* __restrict__ in,
                                                    __half* __restrict__ out, int n4)
{
    int i = blockIdx.x * 256 + threadIdx.x;
    if (i >= n4) return;
    float4 v = ((const float4*)in)[i];
    ((__half2*)out)[i * 2]     = __floats2half2_rn(v.x, v.y);
    ((__half2*)out)[i * 2 + 1] = __floats2half2_rn(v.z, v.w);
}

// ---------------------------------------------------------------------------
// V fp16 [SEQ, DIM] -> Vt fp16 [DIM, SEQ] (transpose)
// ---------------------------------------------------------------------------
__global__ __launch_bounds__(256) void transpose_h(const __half* __restrict__ V,
                                                   __half* __restrict__ Vtf)
{
    __shared__ __half t[32][34];
    const int x0 = blockIdx.x * 32;
    const int y0 = blockIdx.y * 32;
    const int tx = threadIdx.x & 31, ty = threadIdx.x >> 5;
    #pragma unroll
    for (int i = 0; i < 32; i += 8)
        t[ty + i][tx] = V[(size_t)(y0 + ty + i) * DIM + x0 + tx];
    __syncthreads();
    #pragma unroll
    for (int i = 0; i < 32; i += 8)
        Vtf[(size_t)(x0 + ty + i) * SEQ + y0 + tx] = t[tx][ty + i];
}

// ---------------------------------------------------------------------------
// In-place causal softmax; emits attn fp16 for the AV GEMM.
// Zero-fills (fp32 and fp16) only to the next 128 boundary — the strictly
// upper tiles were zero-stored by the scores kernel, and AV truncates K.
// ---------------------------------------------------------------------------
__global__ __launch_bounds__(256) void softmax_causal(float* __restrict__ attn,
                                                      __half* __restrict__ af)
{
    extern __shared__ float row[];
    __shared__ float red[33];

    const int i = blockIdx.x;
    const int n = i + 1;
    const int tid = threadIdx.x;
    float* p = attn + (size_t)i * SEQ;
    __half* pf = af + (size_t)i * SEQ;

    float m = -1e30f;
    for (int j = tid; j < n; j += 256) {
        float v = p[j];
        row[j] = v;
        m = fmaxf(m, v);
    }
    #pragma unroll
    for (int o = 16; o; o >>= 1) m = fmaxf(m, __shfl_xor_sync(0xffffffffu, m, o));
    if ((tid & 31) == 0) red[tid >> 5] = m;
    __syncthreads();
    if (tid < 32) {
        float v = (tid < 8) ? red[tid] : -1e30f;
        #pragma unroll
        for (int o = 4; o; o >>= 1) v = fmaxf(v, __shfl_xor_sync(0xffffffffu, v, o));
        if (tid == 0) red[32] = v;
    }
    __syncthreads();
    const float rowmax = red[32];
    __syncthreads();

    float s = 0.0f;
    for (int j = tid; j < n; j += 256) {
        float e = __expf(row[j] - rowmax);
        row[j] = e;
        s += e;
    }
    #pragma unroll
    for (int o = 16; o; o >>= 1) s += __shfl_xor_sync(0xffffffffu, s, o);
    if ((tid & 31) == 0) red[tid >> 5] = s;
    __syncthreads();
    if (tid < 32) {
        float v = (tid < 8) ? red[tid] : 0.0f;
        #pragma unroll
        for (int o = 4; o; o >>= 1) v += __shfl_xor_sync(0xffffffffu, v, o);
        if (tid == 0) red[32] = v;
    }
    __syncthreads();
    const float inv = 1.0f / red[32];

    for (int j = tid; j < n; j += 256) {
        float v = row[j] * inv;
        p[j] = v;
        pf[j] = __float2half_rn(v);
    }
    const int nend = (n + 127) & ~127;   // diagonal-tile boundary
    const __half z = __float2half_rn(0.0f);
    for (int j = n + tid; j < nend; j += 256) {
        p[j] = 0.0f;
        pf[j] = z;
    }
}

// ---------------------------------------------------------------------------
extern "C" void kernel_launch(void* const* d_in, const int* in_sizes, int n_in,
                              void* d_out, int out_size)
{
    const float* x  = (const float*)d_in[0];
    const float* Wq = (const float*)d_in[1];
    const float* bq = (const float*)d_in[2];
    const float* Wk = (const float*)d_in[3];
    const float* bk = (const float*)d_in[4];
    const float* Wv = (const float*)d_in[5];
    const float* bv = (const float*)d_in[6];

    float* out  = (float*)d_out;                 // [SEQ, DIM]
    float* attn = out + (size_t)SEQ * DIM;       // [SEQ, SEQ]

    __half *xf, *Wqf, *Wkf, *Wvf, *Qf, *Kf, *Vf, *Vtf, *Af;
    cudaGetSymbolAddress((void**)&xf, g_xf);
    cudaGetSymbolAddress((void**)&Wqf, g_Wqf); cudaGetSymbolAddress((void**)&Wkf, g_Wkf);
    cudaGetSymbolAddress((void**)&Wvf, g_Wvf);
    cudaGetSymbolAddress((void**)&Qf, g_Qf);   cudaGetSymbolAddress((void**)&Kf, g_Kf);
    cudaGetSymbolAddress((void**)&Vf, g_Vf);
    cudaGetSymbolAddress((void**)&Vtf, g_Vtf); cudaGetSymbolAddress((void**)&Af, g_Af);

    cudaFuncSetAttribute(mma_gemm<0>, cudaFuncAttributeMaxDynamicSharedMemorySize, GEMM_SMEM);
    cudaFuncSetAttribute(mma_gemm<2>, cudaFuncAttributeMaxDynamicSharedMemorySize, GEMM_SMEM);
    cudaFuncSetAttribute(mma_gemm<3>, cudaFuncAttributeMaxDynamicSharedMemorySize, GEMM_SMEM);

    const float inv_sqrt_d = 0.04419417382415922f;  // 1/sqrt(512)

    // 1) input conversions to fp16
    convert_half<<<(SEQ * DIM / 4 + 255) / 256, 256>>>(x, xf, SEQ * DIM / 4);
    convert_half<<<(DIM * DIM / 4 + 255) / 256, 256>>>(Wq, Wqf, DIM * DIM / 4);
    convert_half<<<(DIM * DIM / 4 + 255) / 256, 256>>>(Wk, Wkf, DIM * DIM / 4);
    convert_half<<<(DIM * DIM / 4 + 255) / 256, 256>>>(Wv, Wvf, DIM * DIM / 4);

    // 2) projections: single-term fp16, fp16 outputs
    dim3 gqkv(DIM / 128, SEQ / 128);
    mma_gemm<0><<<gqkv, 512, GEMM_SMEM>>>(xf, Wqf, bq, nullptr, Qf, DIM, DIM, 1.0f);
    mma_gemm<0><<<gqkv, 512, GEMM_SMEM>>>(xf, Wkf, bk, nullptr, Kf, DIM, DIM, 1.0f);
    mma_gemm<0><<<gqkv, 512, GEMM_SMEM>>>(xf, Wvf, bv, nullptr, Vf, DIM, DIM, 1.0f);

    // 3) V -> Vt (fp16)
    transpose_h<<<dim3(DIM / 32, SEQ / 32), 256>>>(Vf, Vtf);

    // 4) scores: lower tiles MMA+scale; upper tiles zero-store
    dim3 gsc(SEQ / 128, SEQ / 128);
    mma_gemm<2><<<gsc, 512, GEMM_SMEM>>>(Qf, Kf, nullptr, attn, nullptr, SEQ, DIM, inv_sqrt_d);

    // 5) causal softmax (fp32 out + fp16 attn for AV)
    softmax_causal<<<SEQ, 256, SEQ * sizeof(float)>>>(attn, Af);

    // 6) out = attn @ V (K truncated, heavy-first)
    dim3 gav(DIM / 128, SEQ / 128);
    mma_gemm<3><<<gav, 512, GEMM_SMEM>>>(Af, Vtf, nullptr, out, nullptr, DIM, SEQ, 1.0f);
}